// round 2
// baseline (speedup 1.0000x reference)
#include <cuda_runtime.h>

// ---------------------------------------------------------------------------
// ManualCNN: conv(3->16,3x3,p1)+relu+pool2 -> conv(16->32)+relu+pool2 ->
//            conv(32->64)+relu+pool2 -> flatten -> FC(1024->10)
// B = 4096, fp32 everywhere. One image per CTA for the conv stages.
// ---------------------------------------------------------------------------

#define B_MAX 4096

// Intermediate activations (device globals: no allocation allowed).
__device__ float g_h1[B_MAX * 16 * 16 * 16];  // after stage 1 (pooled)
__device__ float g_h2[B_MAX * 32 * 8 * 8];    // after stage 2
__device__ float g_h3[B_MAX * 64 * 4 * 4];    // after stage 3 == [B,1024]

// ---------------------------------------------------------------------------
// Stage 1: conv 3->16 on 32x32, pad 1, relu, maxpool2 -> [16,16,16]
// 256 threads: thread -> (oc = tid>>4, py = tid&15), sweeps px 0..15.
// ---------------------------------------------------------------------------
__global__ __launch_bounds__(256) void conv1_k(const float* __restrict__ x,
                                               const float* __restrict__ w,
                                               const float* __restrict__ bias) {
    // padded input: rows 34 (y=-1..32), row stride 35 (conflict-free for py strides)
    __shared__ float s_in[3][34][35];
    __shared__ float s_w[16 * 27];
    __shared__ float s_b[16];

    const int b = blockIdx.x;
    const int tid = threadIdx.x;

    float* si = &s_in[0][0][0];
    for (int i = tid; i < 3 * 34 * 35; i += 256) si[i] = 0.f;
    for (int i = tid; i < 16 * 27; i += 256) s_w[i] = w[i];
    if (tid < 16) s_b[tid] = bias[tid];
    __syncthreads();

    const float* xb = x + b * 3 * 32 * 32;
    for (int i = tid; i < 3 * 32 * 32; i += 256) {
        int ic = i >> 10, r = (i >> 5) & 31, c = i & 31;
        s_in[ic][r + 1][c + 1] = xb[i];
    }
    __syncthreads();

    const int oc = tid >> 4, py = tid & 15;
    float wreg[27];
#pragma unroll
    for (int j = 0; j < 27; ++j) wreg[j] = s_w[oc * 27 + j];
    const float bb = s_b[oc];

    float* ob = g_h1 + ((b * 16 + oc) * 16 + py) * 16;
    for (int px = 0; px < 16; ++px) {
        float best = -1e30f;
#pragma unroll
        for (int dy = 0; dy < 2; ++dy)
#pragma unroll
            for (int dx = 0; dx < 2; ++dx) {
                float acc = 0.f;
#pragma unroll
                for (int ic = 0; ic < 3; ++ic)
#pragma unroll
                    for (int ky = 0; ky < 3; ++ky)
#pragma unroll
                        for (int kx = 0; kx < 3; ++kx)
                            acc = fmaf(s_in[ic][2 * py + dy + ky][2 * px + dx + kx],
                                       wreg[(ic * 3 + ky) * 3 + kx], acc);
                best = fmaxf(best, acc);
            }
        ob[px] = fmaxf(best + bb, 0.f);
    }
}

// ---------------------------------------------------------------------------
// Stage 2: conv 16->32 on 16x16, pad 1, relu, maxpool2 -> [32,8,8]
// 256 threads: thread -> (oc = tid>>3, py = tid&7), sweeps px 0..7.
// ---------------------------------------------------------------------------
__global__ __launch_bounds__(256) void conv2_k(const float* __restrict__ w,
                                               const float* __restrict__ bias) {
    __shared__ float s_in[16][18][21];   // rows 18 (y=-1..16), stride 21 (conflict-free)
    __shared__ float s_w[32][16][3][3];
    __shared__ float s_b[32];

    const int b = blockIdx.x;
    const int tid = threadIdx.x;

    float* si = &s_in[0][0][0];
    for (int i = tid; i < 16 * 18 * 21; i += 256) si[i] = 0.f;
    float* sw = &s_w[0][0][0][0];
    for (int i = tid; i < 32 * 16 * 9; i += 256) sw[i] = w[i];
    if (tid < 32) s_b[tid] = bias[tid];
    __syncthreads();

    const float* ib = g_h1 + b * 16 * 16 * 16;
    for (int i = tid; i < 16 * 16 * 16; i += 256) {
        int ic = i >> 8, r = (i >> 4) & 15, c = i & 15;
        s_in[ic][r + 1][c + 1] = ib[i];
    }
    __syncthreads();

    const int oc = tid >> 3, py = tid & 7;
    const float bb = s_b[oc];
    float* ob = g_h2 + ((b * 32 + oc) * 8 + py) * 8;

    for (int px = 0; px < 8; ++px) {
        float a00 = 0.f, a01 = 0.f, a10 = 0.f, a11 = 0.f;
#pragma unroll
        for (int ic = 0; ic < 16; ++ic) {
            float p[4][4];
#pragma unroll
            for (int r = 0; r < 4; ++r)
#pragma unroll
                for (int c = 0; c < 4; ++c)
                    p[r][c] = s_in[ic][2 * py + r][2 * px + c];
#pragma unroll
            for (int ky = 0; ky < 3; ++ky)
#pragma unroll
                for (int kx = 0; kx < 3; ++kx) {
                    float wv = s_w[oc][ic][ky][kx];
                    a00 = fmaf(p[ky][kx], wv, a00);
                    a01 = fmaf(p[ky][kx + 1], wv, a01);
                    a10 = fmaf(p[ky + 1][kx], wv, a10);
                    a11 = fmaf(p[ky + 1][kx + 1], wv, a11);
                }
        }
        float best = fmaxf(fmaxf(a00, a01), fmaxf(a10, a11));
        ob[px] = fmaxf(best + bb, 0.f);
    }
}

// ---------------------------------------------------------------------------
// Stage 3: conv 32->64 on 8x8, pad 1, relu, maxpool2 -> [64,4,4]
// Weights (73.7 KB) don't fit static smem: loop 4 groups of 16 ocs.
// 256 threads: per group, thread -> (oc_l = tid>>4, py = (tid>>2)&3, px = tid&3).
// ---------------------------------------------------------------------------
__global__ __launch_bounds__(256) void conv3_k(const float* __restrict__ w,
                                               const float* __restrict__ bias) {
    __shared__ float s_in[32][10][12];   // rows 10 (y=-1..8), stride 12
    __shared__ float s_w[16][32][3][3];  // one 16-oc group at a time
    __shared__ float s_b[64];

    const int b = blockIdx.x;
    const int tid = threadIdx.x;

    float* si = &s_in[0][0][0];
    for (int i = tid; i < 32 * 10 * 12; i += 256) si[i] = 0.f;
    if (tid < 64) s_b[tid] = bias[tid];
    __syncthreads();

    const float* ib = g_h2 + b * 32 * 8 * 8;
    for (int i = tid; i < 32 * 8 * 8; i += 256) {
        int ic = i >> 6, r = (i >> 3) & 7, c = i & 7;
        s_in[ic][r + 1][c + 1] = ib[i];
    }

    float* sw = &s_w[0][0][0][0];
    const int oc_l = tid >> 4, py = (tid >> 2) & 3, px = tid & 3;

    for (int g = 0; g < 4; ++g) {
        __syncthreads();  // (g=0: also fences input load) protect s_w reuse
        for (int i = tid; i < 16 * 32 * 9; i += 256) sw[i] = w[g * 16 * 32 * 9 + i];
        __syncthreads();

        const int oc = g * 16 + oc_l;
        float a00 = 0.f, a01 = 0.f, a10 = 0.f, a11 = 0.f;
#pragma unroll
        for (int ic = 0; ic < 32; ++ic) {
            float p[4][4];
#pragma unroll
            for (int r = 0; r < 4; ++r)
#pragma unroll
                for (int c = 0; c < 4; ++c)
                    p[r][c] = s_in[ic][2 * py + r][2 * px + c];
#pragma unroll
            for (int ky = 0; ky < 3; ++ky)
#pragma unroll
                for (int kx = 0; kx < 3; ++kx) {
                    float wv = s_w[oc_l][ic][ky][kx];
                    a00 = fmaf(p[ky][kx], wv, a00);
                    a01 = fmaf(p[ky][kx + 1], wv, a01);
                    a10 = fmaf(p[ky + 1][kx], wv, a10);
                    a11 = fmaf(p[ky + 1][kx + 1], wv, a11);
                }
        }
        float best = fmaxf(fmaxf(a00, a01), fmaxf(a10, a11));
        g_h3[((b * 64 + oc) * 4 + py) * 4 + px] = fmaxf(best + s_b[oc], 0.f);
    }
}

// ---------------------------------------------------------------------------
// FC: [B,1024] @ fc_w^T [1024,10] + fc_b. One warp per image; 8 images/block.
// ---------------------------------------------------------------------------
__global__ __launch_bounds__(256) void fc_k(const float* __restrict__ w,
                                            const float* __restrict__ bias,
                                            float* __restrict__ out, int B) {
    __shared__ float s_w[10][1024];
    const int tid = threadIdx.x;
    float* sw = &s_w[0][0];
    for (int i = tid; i < 10 * 1024; i += 256) sw[i] = w[i];
    __syncthreads();

    const int warp = tid >> 5, lane = tid & 31;
    const int img = blockIdx.x * 8 + warp;
    if (img >= B) return;

    const float* xr = g_h3 + img * 1024;
    float acc[10];
#pragma unroll
    for (int o = 0; o < 10; ++o) acc[o] = 0.f;

    for (int j = 0; j < 32; ++j) {
        float xv = xr[j * 32 + lane];
#pragma unroll
        for (int o = 0; o < 10; ++o)
            acc[o] = fmaf(xv, s_w[o][j * 32 + lane], acc[o]);
    }
#pragma unroll
    for (int o = 0; o < 10; ++o) {
#pragma unroll
        for (int off = 16; off; off >>= 1)
            acc[o] += __shfl_down_sync(0xffffffffu, acc[o], off);
    }
    if (lane == 0) {
#pragma unroll
        for (int o = 0; o < 10; ++o) out[img * 10 + o] = acc[o] + bias[o];
    }
}

// ---------------------------------------------------------------------------
extern "C" void kernel_launch(void* const* d_in, const int* in_sizes, int n_in,
                              void* d_out, int out_size) {
    const float* x  = (const float*)d_in[0];
    const float* w1 = (const float*)d_in[1];
    const float* b1 = (const float*)d_in[2];
    const float* w2 = (const float*)d_in[3];
    const float* b2 = (const float*)d_in[4];
    const float* w3 = (const float*)d_in[5];
    const float* b3 = (const float*)d_in[6];
    const float* fw = (const float*)d_in[7];
    const float* fb = (const float*)d_in[8];
    float* out = (float*)d_out;

    const int B = in_sizes[0] / (3 * 32 * 32);

    conv1_k<<<B, 256>>>(x, w1, b1);
    conv2_k<<<B, 256>>>(w2, b2);
    conv3_k<<<B, 256>>>(w3, b3);
    fc_k<<<(B + 7) / 8, 256>>>(fw, fb, out, B);
}

// round 3
// speedup vs baseline: 1.1390x; 1.1390x over previous
#include <cuda_runtime.h>

// ---------------------------------------------------------------------------
// ManualCNN: conv(3->16,3x3,p1)+relu+pool2 -> conv(16->32)+relu+pool2 ->
//            conv(32->64)+relu+pool2 -> FC(1024->10).  B=4096, fp32.
// Round 3: packed fp32 FMA (fma.rn.f32x2 / SASS FFMA2). Pool pairs
// (c[2px], c[2px+1]) share weights -> one packed accumulator each.
// ---------------------------------------------------------------------------

#define B_MAX 4096

__device__ float g_h1[B_MAX * 16 * 16 * 16];  // after stage 1 (pooled)
__device__ float g_h2[B_MAX * 32 * 8 * 8];    // after stage 2
__device__ float g_h3[B_MAX * 64 * 4 * 4];    // after stage 3 == [B,1024]

typedef unsigned long long u64;

__device__ __forceinline__ u64 pack2(float lo, float hi) {
    u64 r;
    asm("mov.b64 %0, {%1, %2};" : "=l"(r)
        : "r"(__float_as_uint(lo)), "r"(__float_as_uint(hi)));
    return r;
}
// (a.hi, b.lo) -> odd-parity pair from two adjacent even pairs
__device__ __forceinline__ u64 crossp(u64 a, u64 b) {
    u64 r;
    asm("mov.b64 %0, {%1, %2};" : "=l"(r)
        : "r"((unsigned)(a >> 32)), "r"((unsigned)b));
    return r;
}
__device__ __forceinline__ void fma2(u64& acc, u64 x, u64 w) {
    asm("fma.rn.f32x2 %0, %1, %2, %0;" : "+l"(acc) : "l"(x), "l"(w));
}
__device__ __forceinline__ float lo32(u64 a) { return __uint_as_float((unsigned)a); }
__device__ __forceinline__ float hi32(u64 a) { return __uint_as_float((unsigned)(a >> 32)); }

// ---------------------------------------------------------------------------
// Stage 1: conv 3->16 on 32x32, pad1, relu, pool2 -> [16,16,16]
// 256 thr: oc = tid&15 (low bits: 16-way smem broadcast of rows within warp),
// py = tid>>4. px register-blocked in two halves of 8.
// ---------------------------------------------------------------------------
__global__ __launch_bounds__(256) void conv1_k(const float* __restrict__ x,
                                               const float* __restrict__ w,
                                               const float* __restrict__ bias) {
    __shared__ __align__(16) float s_in[3][34][38];  // rows y=-1..32, stride 38 (even)
    __shared__ float s_w[16 * 28];                   // oc stride 28 (odd-ish banks)
    __shared__ float s_b[16];

    const int b = blockIdx.x, tid = threadIdx.x;

    float* si = &s_in[0][0][0];
    for (int i = tid; i < 3 * 34 * 38; i += 256) si[i] = 0.f;
    for (int i = tid; i < 16 * 27; i += 256) s_w[(i / 27) * 28 + (i % 27)] = w[i];
    if (tid < 16) s_b[tid] = bias[tid];
    __syncthreads();

    const float* xb = x + b * 3 * 32 * 32;
    for (int i = tid; i < 3 * 32 * 32; i += 256) {
        int ic = i >> 10, r = (i >> 5) & 31, c = i & 31;
        s_in[ic][r + 1][c + 1] = xb[i];
    }
    __syncthreads();

    const int oc = tid & 15, py = tid >> 4;
    const float bb = s_b[oc];
    float* ob = g_h1 + ((b * 16 + oc) * 16 + py) * 16;

#pragma unroll
    for (int h = 0; h < 2; ++h) {
        u64 P0[8], P1[8];
#pragma unroll
        for (int q = 0; q < 8; ++q) { P0[q] = 0ull; P1[q] = 0ull; }

#pragma unroll
        for (int ic = 0; ic < 3; ++ic) {
            u64 wp[9];
#pragma unroll
            for (int k = 0; k < 9; ++k) {
                float wv = s_w[oc * 28 + ic * 9 + k];
                wp[k] = pack2(wv, wv);
            }
#pragma unroll
            for (int r = 0; r < 4; ++r) {
                const float* row = &s_in[ic][2 * py + r][16 * h];
                u64 E[9], O[8];
#pragma unroll
                for (int j = 0; j < 9; ++j) E[j] = *(const u64*)(row + 2 * j);
#pragma unroll
                for (int j = 0; j < 8; ++j) O[j] = crossp(E[j], E[j + 1]);
                if (r < 3) {
#pragma unroll
                    for (int q = 0; q < 8; ++q) {
                        fma2(P0[q], E[q],     wp[r * 3 + 0]);
                        fma2(P0[q], O[q],     wp[r * 3 + 1]);
                        fma2(P0[q], E[q + 1], wp[r * 3 + 2]);
                    }
                }
                if (r > 0) {
#pragma unroll
                    for (int q = 0; q < 8; ++q) {
                        fma2(P1[q], E[q],     wp[(r - 1) * 3 + 0]);
                        fma2(P1[q], O[q],     wp[(r - 1) * 3 + 1]);
                        fma2(P1[q], E[q + 1], wp[(r - 1) * 3 + 2]);
                    }
                }
            }
        }
#pragma unroll
        for (int q = 0; q < 8; ++q) {
            float best = fmaxf(fmaxf(lo32(P0[q]), hi32(P0[q])),
                               fmaxf(lo32(P1[q]), hi32(P1[q])));
            ob[8 * h + q] = fmaxf(best + bb, 0.f);
        }
    }
}

// ---------------------------------------------------------------------------
// Stage 2: conv 16->32 on 16x16, pad1, relu, pool2 -> [32,8,8]
// 256 thr: oc = tid>>3, py = tid&7 (4-way oc broadcast of rows). px 0..7 in regs.
// ---------------------------------------------------------------------------
__global__ __launch_bounds__(256) void conv2_k(const float* __restrict__ w,
                                               const float* __restrict__ bias) {
    __shared__ __align__(16) float s_in[16][18][22];  // rows y=-1..16, stride 22
    __shared__ float s_w[32 * 145];                   // oc stride 145 (bank-spread)
    __shared__ float s_b[32];

    const int b = blockIdx.x, tid = threadIdx.x;

    float* si = &s_in[0][0][0];
    for (int i = tid; i < 16 * 18 * 22; i += 256) si[i] = 0.f;
    for (int i = tid; i < 32 * 144; i += 256) s_w[(i / 144) * 145 + (i % 144)] = w[i];
    if (tid < 32) s_b[tid] = bias[tid];
    __syncthreads();

    const float* ib = g_h1 + b * 16 * 16 * 16;
    for (int i = tid; i < 16 * 16 * 16; i += 256) {
        int ic = i >> 8, r = (i >> 4) & 15, c = i & 15;
        s_in[ic][r + 1][c + 1] = ib[i];
    }
    __syncthreads();

    const int oc = tid >> 3, py = tid & 7;
    const float bb = s_b[oc];

    u64 P0[8], P1[8];
#pragma unroll
    for (int q = 0; q < 8; ++q) { P0[q] = 0ull; P1[q] = 0ull; }

    for (int ic = 0; ic < 16; ++ic) {
        u64 wp[9];
#pragma unroll
        for (int k = 0; k < 9; ++k) {
            float wv = s_w[oc * 145 + ic * 9 + k];
            wp[k] = pack2(wv, wv);
        }
#pragma unroll
        for (int r = 0; r < 4; ++r) {
            const float* row = &s_in[ic][2 * py + r][0];
            u64 E[9], O[8];
#pragma unroll
            for (int j = 0; j < 9; ++j) E[j] = *(const u64*)(row + 2 * j);
#pragma unroll
            for (int j = 0; j < 8; ++j) O[j] = crossp(E[j], E[j + 1]);
            if (r < 3) {
#pragma unroll
                for (int q = 0; q < 8; ++q) {
                    fma2(P0[q], E[q],     wp[r * 3 + 0]);
                    fma2(P0[q], O[q],     wp[r * 3 + 1]);
                    fma2(P0[q], E[q + 1], wp[r * 3 + 2]);
                }
            }
            if (r > 0) {
#pragma unroll
                for (int q = 0; q < 8; ++q) {
                    fma2(P1[q], E[q],     wp[(r - 1) * 3 + 0]);
                    fma2(P1[q], O[q],     wp[(r - 1) * 3 + 1]);
                    fma2(P1[q], E[q + 1], wp[(r - 1) * 3 + 2]);
                }
            }
        }
    }

    float* ob = g_h2 + ((b * 32 + oc) * 8 + py) * 8;
#pragma unroll
    for (int q = 0; q < 8; ++q) {
        float best = fmaxf(fmaxf(lo32(P0[q]), hi32(P0[q])),
                           fmaxf(lo32(P1[q]), hi32(P1[q])));
        ob[q] = fmaxf(best + bb, 0.f);
    }
}

// ---------------------------------------------------------------------------
// Stage 3: conv 32->64 on 8x8, pad1, relu, pool2 -> [64,4,4]
// 256 thr: oc = tid>>2 (0..63), py = tid&3. px 0..3 in regs.
// All 64 oc weights in DYNAMIC smem (89.6KB, attribute opt-in), oc stride 289.
// ---------------------------------------------------------------------------
__global__ __launch_bounds__(256) void conv3_k(const float* __restrict__ w,
                                               const float* __restrict__ bias) {
    extern __shared__ __align__(16) float dsm[];
    float* s_in = dsm;                    // 32*10*12 = 3840 floats (stride 12)
    float* s_w  = dsm + 3840;             // 64*289   = 18496 floats
    float* s_b  = dsm + 3840 + 18496;     // 64 floats

    const int b = blockIdx.x, tid = threadIdx.x;

    for (int i = tid; i < 32 * 10 * 12; i += 256) s_in[i] = 0.f;
    for (int i = tid; i < 64 * 288; i += 256) s_w[(i / 288) * 289 + (i % 288)] = w[i];
    if (tid < 64) s_b[tid] = bias[tid];
    __syncthreads();

    const float* ib = g_h2 + b * 32 * 8 * 8;
    for (int i = tid; i < 32 * 8 * 8; i += 256) {
        int ic = i >> 6, r = (i >> 3) & 7, c = i & 7;
        s_in[ic * 120 + (r + 1) * 12 + (c + 1)] = ib[i];
    }
    __syncthreads();

    const int oc = tid >> 2, py = tid & 3;
    const float bb = s_b[oc];

    u64 P0[4], P1[4];
#pragma unroll
    for (int q = 0; q < 4; ++q) { P0[q] = 0ull; P1[q] = 0ull; }

    for (int ic = 0; ic < 32; ++ic) {
        u64 wp[9];
#pragma unroll
        for (int k = 0; k < 9; ++k) {
            float wv = s_w[oc * 289 + ic * 9 + k];
            wp[k] = pack2(wv, wv);
        }
#pragma unroll
        for (int r = 0; r < 4; ++r) {
            const float* row = s_in + ic * 120 + (2 * py + r) * 12;
            u64 E[5], O[4];
#pragma unroll
            for (int j = 0; j < 5; ++j) E[j] = *(const u64*)(row + 2 * j);
#pragma unroll
            for (int j = 0; j < 4; ++j) O[j] = crossp(E[j], E[j + 1]);
            if (r < 3) {
#pragma unroll
                for (int q = 0; q < 4; ++q) {
                    fma2(P0[q], E[q],     wp[r * 3 + 0]);
                    fma2(P0[q], O[q],     wp[r * 3 + 1]);
                    fma2(P0[q], E[q + 1], wp[r * 3 + 2]);
                }
            }
            if (r > 0) {
#pragma unroll
                for (int q = 0; q < 4; ++q) {
                    fma2(P1[q], E[q],     wp[(r - 1) * 3 + 0]);
                    fma2(P1[q], O[q],     wp[(r - 1) * 3 + 1]);
                    fma2(P1[q], E[q + 1], wp[(r - 1) * 3 + 2]);
                }
            }
        }
    }

    float* ob = g_h3 + ((b * 64 + oc) * 4 + py) * 4;
#pragma unroll
    for (int q = 0; q < 4; ++q) {
        float best = fmaxf(fmaxf(lo32(P0[q]), hi32(P0[q])),
                           fmaxf(lo32(P1[q]), hi32(P1[q])));
        ob[q] = fmaxf(best + bb, 0.f);
    }
}

// ---------------------------------------------------------------------------
// FC: [B,1024] @ fc_w^T + fc_b. One warp per image, 8 images/block.
// ---------------------------------------------------------------------------
__global__ __launch_bounds__(256) void fc_k(const float* __restrict__ w,
                                            const float* __restrict__ bias,
                                            float* __restrict__ out, int B) {
    __shared__ float s_w[10][1024];
    const int tid = threadIdx.x;
    float* sw = &s_w[0][0];
    for (int i = tid; i < 10 * 1024; i += 256) sw[i] = w[i];
    __syncthreads();

    const int warp = tid >> 5, lane = tid & 31;
    const int img = blockIdx.x * 8 + warp;
    if (img >= B) return;

    const float* xr = g_h3 + img * 1024;
    float acc[10];
#pragma unroll
    for (int o = 0; o < 10; ++o) acc[o] = 0.f;

    for (int j = 0; j < 32; ++j) {
        float xv = xr[j * 32 + lane];
#pragma unroll
        for (int o = 0; o < 10; ++o)
            acc[o] = fmaf(xv, s_w[o][j * 32 + lane], acc[o]);
    }
#pragma unroll
    for (int o = 0; o < 10; ++o) {
#pragma unroll
        for (int off = 16; off; off >>= 1)
            acc[o] += __shfl_down_sync(0xffffffffu, acc[o], off);
    }
    if (lane == 0) {
#pragma unroll
        for (int o = 0; o < 10; ++o) out[img * 10 + o] = acc[o] + bias[o];
    }
}

// ---------------------------------------------------------------------------
extern "C" void kernel_launch(void* const* d_in, const int* in_sizes, int n_in,
                              void* d_out, int out_size) {
    const float* x  = (const float*)d_in[0];
    const float* w1 = (const float*)d_in[1];
    const float* b1 = (const float*)d_in[2];
    const float* w2 = (const float*)d_in[3];
    const float* b2 = (const float*)d_in[4];
    const float* w3 = (const float*)d_in[5];
    const float* b3 = (const float*)d_in[6];
    const float* fw = (const float*)d_in[7];
    const float* fb = (const float*)d_in[8];
    float* out = (float*)d_out;

    const int B = in_sizes[0] / (3 * 32 * 32);
    const int c3_smem = (3840 + 18496 + 64) * 4;  // 89600 bytes

    cudaFuncSetAttribute(conv3_k, cudaFuncAttributeMaxDynamicSharedMemorySize, c3_smem);

    conv1_k<<<B, 256>>>(x, w1, b1);
    conv2_k<<<B, 256>>>(w2, b2);
    conv3_k<<<B, 256, c3_smem>>>(w3, b3);
    fc_k<<<(B + 7) / 8, 256>>>(fw, fb, out, B);
}

// round 6
// speedup vs baseline: 1.2491x; 1.0966x over previous
#include <cuda_runtime.h>
#include <cuda_fp16.h>
#include <cstdint>

// ---------------------------------------------------------------------------
// ManualCNN round 5: conv2+conv3 via mma.sync (m16n8k16 fp16, 3-product split
// for fp32-grade accuracy). tcgen05 unavailable (compute_103 PTX target).
//   conv1: FFMA2 scalar -> g_h1 NHWC padded [18,18,16], zero ring
//   conv2: warp-MMA shift-GEMM -> g_h2 NHWC padded [10,10,32], zero ring
//   conv3: warp-MMA shift-GEMM -> g_h3 NCHW [64,4,4] flatten
//   fc:    warp-per-image -> out [B,10]
// ---------------------------------------------------------------------------

#define B_MAX 4096

__device__ float g_h1[B_MAX * 324 * 16];   // stage1 out NHWC padded 18x18x16
__device__ float g_h2[B_MAX * 100 * 32];   // stage2 out NHWC padded 10x10x32
__device__ float g_h3[B_MAX * 1024];       // stage3 out NCHW flatten
__device__ half2 g_w2h[2304], g_w2l[2304]; // w2 [tap9][oc32][ic16] hi/lo (half2 over k)
__device__ half2 g_w3h[9216], g_w3l[9216]; // w3 [tap9*2kb][oc64][k16] hi/lo

typedef unsigned long long u64;

// ------------------------------ scalar helpers -----------------------------
__device__ __forceinline__ u64 pack2(float lo, float hi) {
    u64 r;
    asm("mov.b64 %0, {%1, %2};" : "=l"(r)
        : "r"(__float_as_uint(lo)), "r"(__float_as_uint(hi)));
    return r;
}
__device__ __forceinline__ u64 crossp(u64 a, u64 b) {
    u64 r;
    asm("mov.b64 %0, {%1, %2};" : "=l"(r)
        : "r"((unsigned)(a >> 32)), "r"((unsigned)b));
    return r;
}
__device__ __forceinline__ void fma2(u64& acc, u64 x, u64 w) {
    asm("fma.rn.f32x2 %0, %1, %2, %0;" : "+l"(acc) : "l"(x), "l"(w));
}
__device__ __forceinline__ float lo32(u64 a) { return __uint_as_float((unsigned)a); }
__device__ __forceinline__ float hi32(u64 a) { return __uint_as_float((unsigned)(a >> 32)); }

// ------------------------------- mma helper --------------------------------
__device__ __forceinline__ void mma_f16(float d[4], const uint32_t a[4],
                                        const uint32_t b[2]) {
    asm volatile(
        "mma.sync.aligned.m16n8k16.row.col.f32.f16.f16.f32 "
        "{%0,%1,%2,%3}, {%4,%5,%6,%7}, {%8,%9}, {%0,%1,%2,%3};"
        : "+f"(d[0]), "+f"(d[1]), "+f"(d[2]), "+f"(d[3])
        : "r"(a[0]), "r"(a[1]), "r"(a[2]), "r"(a[3]), "r"(b[0]), "r"(b[1]));
}
__device__ __forceinline__ uint32_t ldu32(const half2* p, int i) {
    return *(const uint32_t*)(p + i);
}

// ---------------------------------------------------------------------------
// Stage 1: conv 3->16 on 32x32, pad1, relu, pool2 -> g_h1 NHWC padded
// (FFMA2 scalar path, proven in R3; epilogue retargeted to NHWC + ring zero)
// ---------------------------------------------------------------------------
__global__ __launch_bounds__(256) void conv1_k(const float* __restrict__ x,
                                               const float* __restrict__ w,
                                               const float* __restrict__ bias) {
    __shared__ __align__(16) float s_in[3][34][38];
    __shared__ float s_w[16 * 28];
    __shared__ float s_b[16];

    const int b = blockIdx.x, tid = threadIdx.x;
    float* dst = g_h1 + b * 324 * 16;

    float* si = &s_in[0][0][0];
    for (int i = tid; i < 3 * 34 * 38; i += 256) si[i] = 0.f;
    for (int i = tid; i < 16 * 27; i += 256) s_w[(i / 27) * 28 + (i % 27)] = w[i];
    if (tid < 16) s_b[tid] = bias[tid];

    // zero the NHWC halo ring (68 pixels x 16 ch)
    for (int i = tid; i < 1088; i += 256) {
        int hp = i >> 4, c = i & 15, y, xx;
        if (hp < 18)      { y = 0;       xx = hp; }
        else if (hp < 36) { y = 17;      xx = hp - 18; }
        else if (hp < 52) { y = hp - 35; xx = 0; }
        else              { y = hp - 51; xx = 17; }
        dst[(y * 18 + xx) * 16 + c] = 0.f;
    }
    __syncthreads();

    const float* xb = x + b * 3 * 32 * 32;
    for (int i = tid; i < 3 * 32 * 32; i += 256) {
        int ic = i >> 10, r = (i >> 5) & 31, c = i & 31;
        s_in[ic][r + 1][c + 1] = xb[i];
    }
    __syncthreads();

    const int oc = tid & 15, py = tid >> 4;
    const float bb = s_b[oc];

#pragma unroll
    for (int h = 0; h < 2; ++h) {
        u64 P0[8], P1[8];
#pragma unroll
        for (int q = 0; q < 8; ++q) { P0[q] = 0ull; P1[q] = 0ull; }
#pragma unroll
        for (int ic = 0; ic < 3; ++ic) {
            u64 wp[9];
#pragma unroll
            for (int k = 0; k < 9; ++k) {
                float wv = s_w[oc * 28 + ic * 9 + k];
                wp[k] = pack2(wv, wv);
            }
#pragma unroll
            for (int r = 0; r < 4; ++r) {
                const float* row = &s_in[ic][2 * py + r][16 * h];
                u64 E[9], O[8];
#pragma unroll
                for (int j = 0; j < 9; ++j) E[j] = *(const u64*)(row + 2 * j);
#pragma unroll
                for (int j = 0; j < 8; ++j) O[j] = crossp(E[j], E[j + 1]);
                if (r < 3) {
#pragma unroll
                    for (int q = 0; q < 8; ++q) {
                        fma2(P0[q], E[q],     wp[r * 3 + 0]);
                        fma2(P0[q], O[q],     wp[r * 3 + 1]);
                        fma2(P0[q], E[q + 1], wp[r * 3 + 2]);
                    }
                }
                if (r > 0) {
#pragma unroll
                    for (int q = 0; q < 8; ++q) {
                        fma2(P1[q], E[q],     wp[(r - 1) * 3 + 0]);
                        fma2(P1[q], O[q],     wp[(r - 1) * 3 + 1]);
                        fma2(P1[q], E[q + 1], wp[(r - 1) * 3 + 2]);
                    }
                }
            }
        }
#pragma unroll
        for (int q = 0; q < 8; ++q) {
            float best = fmaxf(fmaxf(lo32(P0[q]), hi32(P0[q])),
                               fmaxf(lo32(P1[q]), hi32(P1[q])));
            dst[((py + 1) * 18 + (8 * h + q + 1)) * 16 + oc] = fmaxf(best + bb, 0.f);
        }
    }
}

// ---------------------------------------------------------------------------
// Weight prep: regroup + fp16 hi/lo split
// ---------------------------------------------------------------------------
__global__ __launch_bounds__(256) void w2prep_k(const float* __restrict__ w2) {
    int p = blockIdx.x * 256 + threadIdx.x;
    if (p >= 2304) return;
    int s = p >> 8, n = (p >> 3) & 31, kp = p & 7;
    int ky = s / 3, kx = s % 3;
    float v0 = w2[((n * 16 + 2 * kp)     * 3 + ky) * 3 + kx];
    float v1 = w2[((n * 16 + 2 * kp + 1) * 3 + ky) * 3 + kx];
    half2 h = __floats2half2_rn(v0, v1);
    float2 hf = __half22float2(h);
    g_w2h[p] = h;
    g_w2l[p] = __floats2half2_rn(v0 - hf.x, v1 - hf.y);
}
__global__ __launch_bounds__(256) void w3prep_k(const float* __restrict__ w3) {
    int p = blockIdx.x * 256 + threadIdx.x;
    if (p >= 9216) return;
    int sIdx = p >> 9, n = (p >> 3) & 63, kp = p & 7;
    int s = sIdx >> 1, kb = sIdx & 1;
    int ky = s / 3, kx = s % 3;
    int ic0 = kb * 16 + 2 * kp;
    float v0 = w3[((n * 32 + ic0)     * 3 + ky) * 3 + kx];
    float v1 = w3[((n * 32 + ic0 + 1) * 3 + ky) * 3 + kx];
    half2 h = __floats2half2_rn(v0, v1);
    float2 hf = __half22float2(h);
    g_w3h[p] = h;
    g_w3l[p] = __floats2half2_rn(v0 - hf.x, v1 - hf.y);
}

// ---------------------------------------------------------------------------
// Stage 2 (mma): conv 16->32 on 16x16 (NHWC 18x18 padded), relu, pool2.
// M = 288 flat pixels (18 m16 tiles, halo cols wasted), N=32 oc, 9 taps K=16.
// Warps: (mq 0..3, np 0..1). smem: Ahi/Alo half2[326*8] chunk-swizzled,
// W half2[2304]x2, staging fp32[288][33].
// ---------------------------------------------------------------------------
#define C2_SMEM_BYTES 77440

__global__ __launch_bounds__(256, 1) void conv2_mma(const float* __restrict__ bias) {
    extern __shared__ __align__(16) char sm2[];
    half2* Ahi = (half2*)sm2;            // 2608
    half2* Alo = Ahi + 2608;             // 2608
    half2* Wh  = Alo + 2608;             // 2304
    half2* Wl  = Wh + 2304;              // 2304
    float* Sg  = (float*)(Wl + 2304);    // 288*33
    float* sb  = Sg + 288 * 33;          // 32

    const int b = blockIdx.x, tid = threadIdx.x;

    for (int i = tid; i < 2304; i += 256) { Wh[i] = g_w2h[i]; Wl[i] = g_w2l[i]; }
    if (tid < 32) sb[tid] = bias[tid];
    if (tid < 16) {  // zero margin pixels qp=0 and qp=325
        int idx = (tid < 8) ? tid : (2600 + tid - 8);
        Ahi[idx] = __floats2half2_rn(0.f, 0.f);
        Alo[idx] = __floats2half2_rn(0.f, 0.f);
    }
    // A build: g_h1 NHWC (ring already zero) -> hi/lo, chunk-swizzled
    const float2* src = (const float2*)(g_h1 + b * 324 * 16);
    for (int i2 = tid; i2 < 324 * 8; i2 += 256) {
        int q = i2 >> 3, jp = i2 & 7, qp = q + 1;
        float2 v = src[i2];
        half2 h = __floats2half2_rn(v.x, v.y);
        float2 hf = __half22float2(h);
        half2 l = __floats2half2_rn(v.x - hf.x, v.y - hf.y);
        int off2 = qp * 8 + (((jp >> 2) ^ (qp & 1)) << 2) + (jp & 3);
        Ahi[off2] = h; Alo[off2] = l;
    }
    __syncthreads();

    const int warp = tid >> 5, lane = tid & 31, g = lane >> 2, t = lane & 3;
    const int mq = warp & 3, np = warp >> 2;

    float d[5][2][4];
#pragma unroll
    for (int im = 0; im < 5; ++im)
#pragma unroll
        for (int nt = 0; nt < 2; ++nt)
#pragma unroll
            for (int k = 0; k < 4; ++k) d[im][nt][k] = 0.f;

#pragma unroll
    for (int s = 0; s < 9; ++s) {
        const int dq = (s / 3 - 1) * 18 + (s % 3 - 1);
        uint32_t bh[2][2], bl[2][2];
#pragma unroll
        for (int nt = 0; nt < 2; ++nt) {
            int widx = (s * 32 + np * 16 + nt * 8 + g) * 8;
            bh[nt][0] = ldu32(Wh, widx + t); bh[nt][1] = ldu32(Wh, widx + 4 + t);
            bl[nt][0] = ldu32(Wl, widx + t); bl[nt][1] = ldu32(Wl, widx + 4 + t);
        }
#pragma unroll
        for (int im = 0; im < 5; ++im) {
            const int mt = mq + 4 * im;
            if (mt >= 18) break;
            const int P = 18 + 16 * mt + g;
            const int qp0 = P + dq + 1, qp1 = qp0 + 8;
            uint32_t ah[4], al[4];
            int o00 = qp0 * 8 + ((qp0 & 1) << 2) + t;
            int o01 = qp0 * 8 + (((qp0 & 1) ^ 1) << 2) + t;
            int o10 = qp1 * 8 + ((qp1 & 1) << 2) + t;
            int o11 = qp1 * 8 + (((qp1 & 1) ^ 1) << 2) + t;
            ah[0] = ldu32(Ahi, o00); ah[1] = ldu32(Ahi, o10);
            ah[2] = ldu32(Ahi, o01); ah[3] = ldu32(Ahi, o11);
            al[0] = ldu32(Alo, o00); al[1] = ldu32(Alo, o10);
            al[2] = ldu32(Alo, o01); al[3] = ldu32(Alo, o11);
#pragma unroll
            for (int nt = 0; nt < 2; ++nt) {
                mma_f16(d[im][nt], ah, bh[nt]);
                mma_f16(d[im][nt], ah, bl[nt]);
                mma_f16(d[im][nt], al, bh[nt]);
            }
        }
    }

    // stage with bias+relu
#pragma unroll
    for (int im = 0; im < 5; ++im) {
        const int mt = mq + 4 * im;
        if (mt >= 18) break;
        const int row = 16 * mt + g;
#pragma unroll
        for (int nt = 0; nt < 2; ++nt) {
            const int col = np * 16 + nt * 8 + 2 * t;
            Sg[row * 33 + col]           = fmaxf(d[im][nt][0] + sb[col], 0.f);
            Sg[row * 33 + col + 1]       = fmaxf(d[im][nt][1] + sb[col + 1], 0.f);
            Sg[(row + 8) * 33 + col]     = fmaxf(d[im][nt][2] + sb[col], 0.f);
            Sg[(row + 8) * 33 + col + 1] = fmaxf(d[im][nt][3] + sb[col + 1], 0.f);
        }
    }
    __syncthreads();

    // pool -> g_h2 NHWC padded; + ring zero
    float* dst = g_h2 + b * 100 * 32;
    for (int e = tid; e < 2048; e += 256) {
        int oc = e & 31, pp = e >> 5, py = pp >> 3, px = pp & 7;
        int p = 18 * (2 * py + 1) + (2 * px + 1);
        int r0 = p - 18;
        float v = fmaxf(fmaxf(Sg[r0 * 33 + oc], Sg[(r0 + 1) * 33 + oc]),
                        fmaxf(Sg[(r0 + 18) * 33 + oc], Sg[(r0 + 19) * 33 + oc]));
        dst[((py + 1) * 10 + (px + 1)) * 32 + oc] = v;
    }
    for (int i = tid; i < 36 * 32; i += 256) {
        int hp = i >> 5, c = i & 31, y, xx;
        if (hp < 10)      { y = 0;       xx = hp; }
        else if (hp < 20) { y = 9;       xx = hp - 10; }
        else if (hp < 28) { y = hp - 19; xx = 0; }
        else              { y = hp - 27; xx = 9; }
        dst[(y * 10 + xx) * 32 + c] = 0.f;
    }
}

// ---------------------------------------------------------------------------
// Stage 3 (mma): conv 32->64 on 8x8 (NHWC 10x10 padded), relu, pool2.
// M = 96 flat pixels (6 m16 tiles), N=64 oc, 18 (tap,kb) K=16 blocks.
// Warps: (mh 0..1, np 0..3). A chunk-swizzled by (qp&3).
// ---------------------------------------------------------------------------
#define C3_SMEM_BYTES 114048

__global__ __launch_bounds__(256, 1) void conv3_mma(const float* __restrict__ bias) {
    extern __shared__ __align__(16) char sm3[];
    half2* Ahi = (half2*)sm3;            // 1888 (118 px * 16)
    half2* Alo = Ahi + 1888;
    half2* Wh  = Alo + 1888;             // 9216
    half2* Wl  = Wh + 9216;
    float* Sg  = (float*)(Wl + 9216);    // 96*65
    float* sb  = Sg + 96 * 65;           // 64

    const int b = blockIdx.x, tid = threadIdx.x;

    for (int i = tid; i < 9216; i += 256) { Wh[i] = g_w3h[i]; Wl[i] = g_w3l[i]; }
    if (tid < 64) sb[tid] = bias[tid];
    // zero margin pixels qp 0..2 and 103..117
    for (int i = tid; i < 288; i += 256) {
        int idx = i >> 4, qp = (idx < 3) ? idx : (100 + idx);
        Ahi[qp * 16 + (i & 15)] = __floats2half2_rn(0.f, 0.f);
        Alo[qp * 16 + (i & 15)] = __floats2half2_rn(0.f, 0.f);
    }
    const float2* src = (const float2*)(g_h2 + b * 100 * 32);
    for (int i2 = tid; i2 < 1600; i2 += 256) {
        int q = i2 >> 4, jp = i2 & 15, qp = q + 3;
        float2 v = src[i2];
        half2 h = __floats2half2_rn(v.x, v.y);
        float2 hf = __half22float2(h);
        half2 l = __floats2half2_rn(v.x - hf.x, v.y - hf.y);
        int off2 = qp * 16 + (((jp >> 2) ^ (qp & 3)) << 2) + (jp & 3);
        Ahi[off2] = h; Alo[off2] = l;
    }
    __syncthreads();

    const int warp = tid >> 5, lane = tid & 31, g = lane >> 2, t = lane & 3;
    const int mh = warp & 1, np = warp >> 1;

    float d[3][2][4];
#pragma unroll
    for (int im = 0; im < 3; ++im)
#pragma unroll
        for (int nt = 0; nt < 2; ++nt)
#pragma unroll
            for (int k = 0; k < 4; ++k) d[im][nt][k] = 0.f;

#pragma unroll
    for (int sIdx = 0; sIdx < 18; ++sIdx) {
        const int s = sIdx >> 1, kb = sIdx & 1;
        const int dq = (s / 3 - 1) * 10 + (s % 3 - 1);
        uint32_t bh[2][2], bl[2][2];
#pragma unroll
        for (int nt = 0; nt < 2; ++nt) {
            int widx = (sIdx * 64 + np * 16 + nt * 8 + g) * 8;
            bh[nt][0] = ldu32(Wh, widx + t); bh[nt][1] = ldu32(Wh, widx + 4 + t);
            bl[nt][0] = ldu32(Wl, widx + t); bl[nt][1] = ldu32(Wl, widx + 4 + t);
        }
#pragma unroll
        for (int im = 0; im < 3; ++im) {
            const int mt = mh + 2 * im;
            const int P = 8 + 16 * mt + g;
            const int qp0 = P + dq + 3, qp1 = qp0 + 8;
            const int c0 = 2 * kb, c1 = 2 * kb + 1;
            uint32_t ah[4], al[4];
            int o00 = qp0 * 16 + ((c0 ^ (qp0 & 3)) << 2) + t;
            int o01 = qp0 * 16 + ((c1 ^ (qp0 & 3)) << 2) + t;
            int o10 = qp1 * 16 + ((c0 ^ (qp1 & 3)) << 2) + t;
            int o11 = qp1 * 16 + ((c1 ^ (qp1 & 3)) << 2) + t;
            ah[0] = ldu32(Ahi, o00); ah[1] = ldu32(Ahi, o10);
            ah[2] = ldu32(Ahi, o01); ah[3] = ldu32(Ahi, o11);
            al[0] = ldu32(Alo, o00); al[1] = ldu32(Alo, o10);
            al[2] = ldu32(Alo, o01); al[3] = ldu32(Alo, o11);
#pragma unroll
            for (int nt = 0; nt < 2; ++nt) {
                mma_f16(d[im][nt], ah, bh[nt]);
                mma_f16(d[im][nt], ah, bl[nt]);
                mma_f16(d[im][nt], al, bh[nt]);
            }
        }
    }

#pragma unroll
    for (int im = 0; im < 3; ++im) {
        const int row = 16 * (mh + 2 * im) + g;
#pragma unroll
        for (int nt = 0; nt < 2; ++nt) {
            const int col = np * 16 + nt * 8 + 2 * t;
            Sg[row * 65 + col]           = fmaxf(d[im][nt][0] + sb[col], 0.f);
            Sg[row * 65 + col + 1]       = fmaxf(d[im][nt][1] + sb[col + 1], 0.f);
            Sg[(row + 8) * 65 + col]     = fmaxf(d[im][nt][2] + sb[col], 0.f);
            Sg[(row + 8) * 65 + col + 1] = fmaxf(d[im][nt][3] + sb[col + 1], 0.f);
        }
    }
    __syncthreads();

    // pool -> g_h3 NCHW flatten
    for (int e = tid; e < 1024; e += 256) {
        int oc = e >> 4, pp = e & 15, py = pp >> 2, px = pp & 3;
        int p = 10 * (2 * py + 1) + (2 * px + 1);
        int r0 = p - 8;
        float v = fmaxf(fmaxf(Sg[r0 * 65 + oc], Sg[(r0 + 1) * 65 + oc]),
                        fmaxf(Sg[(r0 + 10) * 65 + oc], Sg[(r0 + 11) * 65 + oc]));
        g_h3[b * 1024 + oc * 16 + pp] = v;
    }
}

// ---------------------------------------------------------------------------
// FC: [B,1024] @ fc_w^T + fc_b. One warp per image, 8 images/block.
// ---------------------------------------------------------------------------
__global__ __launch_bounds__(256) void fc_k(const float* __restrict__ w,
                                            const float* __restrict__ bias,
                                            float* __restrict__ out, int B) {
    __shared__ float s_w[10][1024];
    const int tid = threadIdx.x;
    float* sw = &s_w[0][0];
    for (int i = tid; i < 10 * 1024; i += 256) sw[i] = w[i];
    __syncthreads();

    const int warp = tid >> 5, lane = tid & 31;
    const int img = blockIdx.x * 8 + warp;
    if (img >= B) return;

    const float* xr = g_h3 + img * 1024;
    float acc[10];
#pragma unroll
    for (int o = 0; o < 10; ++o) acc[o] = 0.f;

    for (int j = 0; j < 32; ++j) {
        float xv = xr[j * 32 + lane];
#pragma unroll
        for (int o = 0; o < 10; ++o)
            acc[o] = fmaf(xv, s_w[o][j * 32 + lane], acc[o]);
    }
#pragma unroll
    for (int o = 0; o < 10; ++o) {
#pragma unroll
        for (int off = 16; off; off >>= 1)
            acc[o] += __shfl_down_sync(0xffffffffu, acc[o], off);
    }
    if (lane == 0) {
#pragma unroll
        for (int o = 0; o < 10; ++o) out[img * 10 + o] = acc[o] + bias[o];
    }
}

// ---------------------------------------------------------------------------
extern "C" void kernel_launch(void* const* d_in, const int* in_sizes, int n_in,
                              void* d_out, int out_size) {
    const float* x  = (const float*)d_in[0];
    const float* w1 = (const float*)d_in[1];
    const float* b1 = (const float*)d_in[2];
    const float* w2 = (const float*)d_in[3];
    const float* b2 = (const float*)d_in[4];
    const float* w3 = (const float*)d_in[5];
    const float* b3 = (const float*)d_in[6];
    const float* fw = (const float*)d_in[7];
    const float* fb = (const float*)d_in[8];
    float* out = (float*)d_out;

    const int B = in_sizes[0] / (3 * 32 * 32);

    cudaFuncSetAttribute(conv2_mma, cudaFuncAttributeMaxDynamicSharedMemorySize,
                         C2_SMEM_BYTES);
    cudaFuncSetAttribute(conv3_mma, cudaFuncAttributeMaxDynamicSharedMemorySize,
                         C3_SMEM_BYTES);

    w2prep_k<<<9, 256>>>(w2);
    w3prep_k<<<36, 256>>>(w3);
    conv1_k<<<B, 256>>>(x, w1, b1);
    conv2_mma<<<B, 256, C2_SMEM_BYTES>>>(b2);
    conv3_mma<<<B, 256, C3_SMEM_BYTES>>>(b3);
    fc_k<<<(B + 7) / 8, 256>>>(fw, fb, out, B);
}

// round 7
// speedup vs baseline: 1.5055x; 1.2053x over previous
#include <cuda_runtime.h>
#include <cuda_fp16.h>
#include <cstdint>

// ---------------------------------------------------------------------------
// ManualCNN round 6: mma.sync convs with ldmatrix + fragment-packed B +
// smem aliasing (2 CTAs/SM).
//   conv1: FFMA2 scalar -> g_h1 NHWC padded [18,18,16], zero ring
//   conv2: warp-MMA shift-GEMM -> g_h2 NHWC padded [10,10,32], zero ring
//   conv3: warp-MMA shift-GEMM -> g_h3 NCHW [64,4,4] flatten
//   fc:    warp-per-image -> out [B,10]
// 3-product fp16 split (Ahi*Bhi + Ahi*Blo + Alo*Bhi), fp32 accum.
// ---------------------------------------------------------------------------

#define B_MAX 4096

__device__ float g_h1[B_MAX * 324 * 16];
__device__ float g_h2[B_MAX * 100 * 32];
__device__ float g_h3[B_MAX * 1024];
__device__ uint4 g_w2pk[1152];   // [hi 576 | lo 576] fragment-packed w2
__device__ uint4 g_w3pk[4608];   // [hi 2304 | lo 2304] fragment-packed w3

typedef unsigned long long u64;

// ------------------------------ scalar helpers -----------------------------
__device__ __forceinline__ u64 pack2(float lo, float hi) {
    u64 r;
    asm("mov.b64 %0, {%1, %2};" : "=l"(r)
        : "r"(__float_as_uint(lo)), "r"(__float_as_uint(hi)));
    return r;
}
__device__ __forceinline__ u64 crossp(u64 a, u64 b) {
    u64 r;
    asm("mov.b64 %0, {%1, %2};" : "=l"(r)
        : "r"((unsigned)(a >> 32)), "r"((unsigned)b));
    return r;
}
__device__ __forceinline__ void fma2(u64& acc, u64 x, u64 w) {
    asm("fma.rn.f32x2 %0, %1, %2, %0;" : "+l"(acc) : "l"(x), "l"(w));
}
__device__ __forceinline__ float lo32(u64 a) { return __uint_as_float((unsigned)a); }
__device__ __forceinline__ float hi32(u64 a) { return __uint_as_float((unsigned)(a >> 32)); }

// ------------------------------- mma helpers -------------------------------
__device__ __forceinline__ void mma_f16(float d[4], const uint32_t a[4],
                                        uint32_t b0, uint32_t b1) {
    asm volatile(
        "mma.sync.aligned.m16n8k16.row.col.f32.f16.f16.f32 "
        "{%0,%1,%2,%3}, {%4,%5,%6,%7}, {%8,%9}, {%0,%1,%2,%3};"
        : "+f"(d[0]), "+f"(d[1]), "+f"(d[2]), "+f"(d[3])
        : "r"(a[0]), "r"(a[1]), "r"(a[2]), "r"(a[3]), "r"(b0), "r"(b1));
}
__device__ __forceinline__ void ldmx4(uint32_t r[4], uint32_t addr) {
    asm volatile("ldmatrix.sync.aligned.m8n8.x4.shared.b16 {%0,%1,%2,%3}, [%4];"
                 : "=r"(r[0]), "=r"(r[1]), "=r"(r[2]), "=r"(r[3]) : "r"(addr));
}
__device__ __forceinline__ uint32_t smem_u32(const void* p) {
    uint32_t a;
    asm("{ .reg .u64 t; cvta.to.shared.u64 t, %1; cvt.u32.u64 %0, t; }"
        : "=r"(a) : "l"(p));
    return a;
}

// ---------------------------------------------------------------------------
// Stage 1: conv 3->16 on 32x32, pad1, relu, pool2 -> g_h1 NHWC padded
// ---------------------------------------------------------------------------
__global__ __launch_bounds__(256) void conv1_k(const float* __restrict__ x,
                                               const float* __restrict__ w,
                                               const float* __restrict__ bias) {
    __shared__ __align__(16) float s_in[3][34][38];
    __shared__ float s_w[16 * 28];
    __shared__ float s_b[16];

    const int b = blockIdx.x, tid = threadIdx.x;
    float* dst = g_h1 + b * 324 * 16;

    float* si = &s_in[0][0][0];
    for (int i = tid; i < 3 * 34 * 38; i += 256) si[i] = 0.f;
    for (int i = tid; i < 16 * 27; i += 256) s_w[(i / 27) * 28 + (i % 27)] = w[i];
    if (tid < 16) s_b[tid] = bias[tid];

    for (int i = tid; i < 1088; i += 256) {  // zero halo ring
        int hp = i >> 4, c = i & 15, y, xx;
        if (hp < 18)      { y = 0;       xx = hp; }
        else if (hp < 36) { y = 17;      xx = hp - 18; }
        else if (hp < 52) { y = hp - 35; xx = 0; }
        else              { y = hp - 51; xx = 17; }
        dst[(y * 18 + xx) * 16 + c] = 0.f;
    }
    __syncthreads();

    const float* xb = x + b * 3 * 32 * 32;
    for (int i = tid; i < 3 * 32 * 32; i += 256) {
        int ic = i >> 10, r = (i >> 5) & 31, c = i & 31;
        s_in[ic][r + 1][c + 1] = xb[i];
    }
    __syncthreads();

    const int oc = tid & 15, py = tid >> 4;
    const float bb = s_b[oc];

#pragma unroll
    for (int h = 0; h < 2; ++h) {
        u64 P0[8], P1[8];
#pragma unroll
        for (int q = 0; q < 8; ++q) { P0[q] = 0ull; P1[q] = 0ull; }
#pragma unroll
        for (int ic = 0; ic < 3; ++ic) {
            u64 wp[9];
#pragma unroll
            for (int k = 0; k < 9; ++k) {
                float wv = s_w[oc * 28 + ic * 9 + k];
                wp[k] = pack2(wv, wv);
            }
#pragma unroll
            for (int r = 0; r < 4; ++r) {
                const float* row = &s_in[ic][2 * py + r][16 * h];
                u64 E[9], O[8];
#pragma unroll
                for (int j = 0; j < 9; ++j) E[j] = *(const u64*)(row + 2 * j);
#pragma unroll
                for (int j = 0; j < 8; ++j) O[j] = crossp(E[j], E[j + 1]);
                if (r < 3) {
#pragma unroll
                    for (int q = 0; q < 8; ++q) {
                        fma2(P0[q], E[q],     wp[r * 3 + 0]);
                        fma2(P0[q], O[q],     wp[r * 3 + 1]);
                        fma2(P0[q], E[q + 1], wp[r * 3 + 2]);
                    }
                }
                if (r > 0) {
#pragma unroll
                    for (int q = 0; q < 8; ++q) {
                        fma2(P1[q], E[q],     wp[(r - 1) * 3 + 0]);
                        fma2(P1[q], O[q],     wp[(r - 1) * 3 + 1]);
                        fma2(P1[q], E[q + 1], wp[(r - 1) * 3 + 2]);
                    }
                }
            }
        }
#pragma unroll
        for (int q = 0; q < 8; ++q) {
            float best = fmaxf(fmaxf(lo32(P0[q]), hi32(P0[q])),
                               fmaxf(lo32(P1[q]), hi32(P1[q])));
            dst[((py + 1) * 18 + (8 * h + q + 1)) * 16 + oc] = fmaxf(best + bb, 0.f);
        }
    }
}

// ---------------------------------------------------------------------------
// Weight prep: fragment-packed order + fp16 hi/lo split.
// B-frag lane map (m16n8k16): lane l -> g=l>>2 (n within 8), t=l&3 (k pair).
// ---------------------------------------------------------------------------
__global__ __launch_bounds__(256) void w2prep_k(const float* __restrict__ w2) {
    int p = blockIdx.x * 256 + threadIdx.x;
    if (p >= 2304) return;                       // [s9][h2][lane32][e4]
    int s = p >> 8, h = (p >> 7) & 1, l = (p >> 2) & 31, e = p & 3;
    int g = l >> 2, t = l & 3;
    int ky = s / 3, kx = s % 3;
    int oc = (h * 2 + (e >> 1)) * 8 + g;
    int k0 = 2 * t + 8 * (e & 1);
    float v0 = w2[((oc * 16 + k0)     * 3 + ky) * 3 + kx];
    float v1 = w2[((oc * 16 + k0 + 1) * 3 + ky) * 3 + kx];
    half2 hi = __floats2half2_rn(v0, v1);
    float2 hf = __half22float2(hi);
    ((half2*)g_w2pk)[p]        = hi;
    ((half2*)g_w2pk)[2304 + p] = __floats2half2_rn(v0 - hf.x, v1 - hf.y);
}
__global__ __launch_bounds__(256) void w3prep_k(const float* __restrict__ w3) {
    int p = blockIdx.x * 256 + threadIdx.x;
    if (p >= 9216) return;                       // [sIdx18][np4][lane32][e4]
    int sIdx = p >> 9, np = (p >> 7) & 3, l = (p >> 2) & 31, e = p & 3;
    int g = l >> 2, t = l & 3;
    int s = sIdx >> 1, kb = sIdx & 1;
    int ky = s / 3, kx = s % 3;
    int oc = np * 16 + (e >> 1) * 8 + g;
    int k0 = kb * 16 + 2 * t + 8 * (e & 1);
    float v0 = w3[((oc * 32 + k0)     * 3 + ky) * 3 + kx];
    float v1 = w3[((oc * 32 + k0 + 1) * 3 + ky) * 3 + kx];
    half2 hi = __floats2half2_rn(v0, v1);
    float2 hf = __half22float2(hi);
    ((half2*)g_w3pk)[p]        = hi;
    ((half2*)g_w3pk)[9216 + p] = __floats2half2_rn(v0 - hf.x, v1 - hf.y);
}

// ---------------------------------------------------------------------------
// Stage 2 (mma): conv 16->32, M=288 flat px (tiles 18), N=32, 9 taps K=16.
// Warp w: all 32 oc, m-tiles {w, w+8, w+16<18}. A pixel stride 48B (odd 16B).
// smem: [W 18432 | sb 128 | union(A hi/lo 31296, Sg 38016)] = 56576 B.
// ---------------------------------------------------------------------------
#define C2_SMEM 56576

__global__ __launch_bounds__(256, 2) void conv2_mma(const float* __restrict__ bias) {
    extern __shared__ __align__(16) char sm[];
    const uint4* W4 = (const uint4*)sm;
    float* sb  = (float*)(sm + 18432);
    half2* Ahi = (half2*)(sm + 18560);   // 326 px * 12 half2 (48B stride)
    half2* Alo = (half2*)(sm + 34208);
    float* Sg  = (float*)(sm + 18560);   // aliases A after mainloop

    const int b = blockIdx.x, tid = threadIdx.x;
    const int lane = tid & 31, wid = tid >> 5;

    {
        uint4* d = (uint4*)sm;
        for (int i = tid; i < 1152; i += 256) d[i] = g_w2pk[i];
    }
    if (tid < 32) sb[tid] = bias[tid];

    float* dsth2 = g_h2 + b * 100 * 32;
    for (int i = tid; i < 1152; i += 256) {  // zero g_h2 halo ring
        int hp = i >> 5, c = i & 31, y, xx;
        if (hp < 10)      { y = 0;       xx = hp; }
        else if (hp < 20) { y = 9;       xx = hp - 10; }
        else if (hp < 28) { y = hp - 19; xx = 0; }
        else              { y = hp - 27; xx = 9; }
        dsth2[(y * 10 + xx) * 32 + c] = 0.f;
    }
    if (tid < 24) {  // zero A margin pixels qp=0, qp=325
        int idx = (tid < 12) ? tid : (325 * 12 + tid - 12);
        Ahi[idx] = __floats2half2_rn(0.f, 0.f);
        Alo[idx] = __floats2half2_rn(0.f, 0.f);
    }
    const float2* src = (const float2*)(g_h1 + b * 324 * 16);
    for (int i2 = tid; i2 < 2592; i2 += 256) {
        int p = i2 >> 3, j = i2 & 7;
        float2 v = src[i2];
        half2 h = __floats2half2_rn(v.x, v.y);
        float2 hf = __half22float2(h);
        Ahi[(p + 1) * 12 + j] = h;
        Alo[(p + 1) * 12 + j] = __floats2half2_rn(v.x - hf.x, v.y - hf.y);
    }
    __syncthreads();

    const uint32_t smb = smem_u32(sm);
    const uint32_t aHiB = smb + 18560 + (lane & 15) * 48 + (lane >> 4) * 16;
    const uint32_t aLoB = smb + 34208 + (lane & 15) * 48 + (lane >> 4) * 16;

    float d[3][4][4];
#pragma unroll
    for (int i = 0; i < 3; ++i)
#pragma unroll
        for (int nt = 0; nt < 4; ++nt)
#pragma unroll
            for (int k = 0; k < 4; ++k) d[i][nt][k] = 0.f;

#pragma unroll
    for (int s = 0; s < 9; ++s) {
        const uint4 h0 = W4[(s * 2 + 0) * 32 + lane];
        const uint4 h1 = W4[(s * 2 + 1) * 32 + lane];
        const uint4 l0 = W4[576 + (s * 2 + 0) * 32 + lane];
        const uint4 l1 = W4[576 + (s * 2 + 1) * 32 + lane];
        const uint32_t bh[4][2] = {{h0.x, h0.y}, {h0.z, h0.w}, {h1.x, h1.y}, {h1.z, h1.w}};
        const uint32_t bl[4][2] = {{l0.x, l0.y}, {l0.z, l0.w}, {l1.x, l1.y}, {l1.z, l1.w}};
        const int rowc = (18 + (s / 3 - 1) * 18 + (s % 3 - 1) + 1) * 48;
#pragma unroll
        for (int i = 0; i < 3; ++i) {
            const int mt = wid + 8 * i;
            if (mt < 18) {
                uint32_t ah[4], al[4];
                ldmx4(ah, aHiB + rowc + mt * 768);
                ldmx4(al, aLoB + rowc + mt * 768);
#pragma unroll
                for (int nt = 0; nt < 4; ++nt) {
                    mma_f16(d[i][nt], ah, bh[nt][0], bh[nt][1]);
                    mma_f16(d[i][nt], ah, bl[nt][0], bl[nt][1]);
                    mma_f16(d[i][nt], al, bh[nt][0], bh[nt][1]);
                }
            }
        }
    }
    __syncthreads();  // A buffers dead -> Sg may overwrite

    const int g = lane >> 2, t = lane & 3;
#pragma unroll
    for (int i = 0; i < 3; ++i) {
        const int mt = wid + 8 * i;
        if (mt < 18) {
            const int row = 16 * mt + g;
#pragma unroll
            for (int nt = 0; nt < 4; ++nt) {
                const int col = nt * 8 + 2 * t;
                Sg[row * 33 + col]           = fmaxf(d[i][nt][0] + sb[col], 0.f);
                Sg[row * 33 + col + 1]       = fmaxf(d[i][nt][1] + sb[col + 1], 0.f);
                Sg[(row + 8) * 33 + col]     = fmaxf(d[i][nt][2] + sb[col], 0.f);
                Sg[(row + 8) * 33 + col + 1] = fmaxf(d[i][nt][3] + sb[col + 1], 0.f);
            }
        }
    }
    __syncthreads();

    for (int e = tid; e < 2048; e += 256) {  // pool -> g_h2 NHWC padded
        int oc = e & 31, pp = e >> 5, py = pp >> 3, px = pp & 7;
        int r0 = 18 * (2 * py + 1) + (2 * px + 1) - 18;
        float v = fmaxf(fmaxf(Sg[r0 * 33 + oc], Sg[(r0 + 1) * 33 + oc]),
                        fmaxf(Sg[(r0 + 18) * 33 + oc], Sg[(r0 + 19) * 33 + oc]));
        dsth2[((py + 1) * 10 + (px + 1)) * 32 + oc] = v;
    }
}

// ---------------------------------------------------------------------------
// Stage 3 (mma): conv 32->64, M=96 flat px (tiles 6), N=64, 18 (tap,kb) K=16.
// Warp w: np=w&3 (16 oc), mh=w>>2, m-tiles {mh, mh+2, mh+4}. A stride 80B.
// smem: [W 73728 | sb 256 | union(A 18880, Sg 24960)] = 98944 B.
// ---------------------------------------------------------------------------
#define C3_SMEM 98944

__global__ __launch_bounds__(256, 2) void conv3_mma(const float* __restrict__ bias) {
    extern __shared__ __align__(16) char sm[];
    const uint4* W4 = (const uint4*)sm;
    float* sb  = (float*)(sm + 73728);
    half2* Ahi = (half2*)(sm + 73984);   // 118 px * 20 half2 (80B stride)
    half2* Alo = (half2*)(sm + 83424);
    float* Sg  = (float*)(sm + 73984);   // aliases A after mainloop

    const int b = blockIdx.x, tid = threadIdx.x;
    const int lane = tid & 31, wid = tid >> 5;

    {
        uint4* d = (uint4*)sm;
        for (int i = tid; i < 4608; i += 256) d[i] = g_w3pk[i];
    }
    if (tid < 64) sb[tid] = bias[tid];

    for (int i = tid; i < 360; i += 256) {  // zero A margins qp 0..2, 103..117
        int pxi = i / 20, j = i % 20;
        int qp = (pxi < 3) ? pxi : (100 + pxi);
        Ahi[qp * 20 + j] = __floats2half2_rn(0.f, 0.f);
        Alo[qp * 20 + j] = __floats2half2_rn(0.f, 0.f);
    }
    const float2* src = (const float2*)(g_h2 + b * 100 * 32);
    for (int i2 = tid; i2 < 1600; i2 += 256) {
        int p = i2 >> 4, j = i2 & 15;
        float2 v = src[i2];
        half2 h = __floats2half2_rn(v.x, v.y);
        float2 hf = __half22float2(h);
        Ahi[(p + 3) * 20 + j] = h;
        Alo[(p + 3) * 20 + j] = __floats2half2_rn(v.x - hf.x, v.y - hf.y);
    }
    __syncthreads();

    const uint32_t smb = smem_u32(sm);
    const uint32_t aHiB = smb + 73984 + (lane & 15) * 80 + (lane >> 4) * 16;
    const uint32_t aLoB = smb + 83424 + (lane & 15) * 80 + (lane >> 4) * 16;
    const int np = wid & 3, mh = wid >> 2;

    float d[3][2][4];
#pragma unroll
    for (int i = 0; i < 3; ++i)
#pragma unroll
        for (int nt = 0; nt < 2; ++nt)
#pragma unroll
            for (int k = 0; k < 4; ++k) d[i][nt][k] = 0.f;

#pragma unroll
    for (int sIdx = 0; sIdx < 18; ++sIdx) {
        const int s = sIdx >> 1, kb = sIdx & 1;
        const uint4 h4 = W4[(sIdx * 4 + np) * 32 + lane];
        const uint4 l4 = W4[2304 + (sIdx * 4 + np) * 32 + lane];
        const uint32_t bh[2][2] = {{h4.x, h4.y}, {h4.z, h4.w}};
        const uint32_t bl[2][2] = {{l4.x, l4.y}, {l4.z, l4.w}};
        const int rowc = (8 + (s / 3 - 1) * 10 + (s % 3 - 1) + 3) * 80 + kb * 32;
#pragma unroll
        for (int i = 0; i < 3; ++i) {
            const int mt = mh + 2 * i;
            uint32_t ah[4], al[4];
            ldmx4(ah, aHiB + rowc + mt * 1280);
            ldmx4(al, aLoB + rowc + mt * 1280);
#pragma unroll
            for (int nt = 0; nt < 2; ++nt) {
                mma_f16(d[i][nt], ah, bh[nt][0], bh[nt][1]);
                mma_f16(d[i][nt], ah, bl[nt][0], bl[nt][1]);
                mma_f16(d[i][nt], al, bh[nt][0], bh[nt][1]);
            }
        }
    }
    __syncthreads();  // A dead -> Sg alias

    const int g = lane >> 2, t = lane & 3;
#pragma unroll
    for (int i = 0; i < 3; ++i) {
        const int row = 16 * (mh + 2 * i) + g;
#pragma unroll
        for (int nt = 0; nt < 2; ++nt) {
            const int col = np * 16 + nt * 8 + 2 * t;
            Sg[row * 65 + col]           = fmaxf(d[i][nt][0] + sb[col], 0.f);
            Sg[row * 65 + col + 1]       = fmaxf(d[i][nt][1] + sb[col + 1], 0.f);
            Sg[(row + 8) * 65 + col]     = fmaxf(d[i][nt][2] + sb[col], 0.f);
            Sg[(row + 8) * 65 + col + 1] = fmaxf(d[i][nt][3] + sb[col + 1], 0.f);
        }
    }
    __syncthreads();

    for (int e = tid; e < 1024; e += 256) {  // pool -> g_h3 NCHW flatten
        int oc = e >> 4, pp = e & 15, py = pp >> 2, px = pp & 3;
        int r0 = 10 * (2 * py + 1) + (2 * px + 1) - 8;
        float v = fmaxf(fmaxf(Sg[r0 * 65 + oc], Sg[(r0 + 1) * 65 + oc]),
                        fmaxf(Sg[(r0 + 10) * 65 + oc], Sg[(r0 + 11) * 65 + oc]));
        g_h3[b * 1024 + oc * 16 + pp] = v;
    }
}

// ---------------------------------------------------------------------------
// FC: [B,1024] @ fc_w^T + fc_b. One warp per image, 8 images/block.
// ---------------------------------------------------------------------------
__global__ __launch_bounds__(256) void fc_k(const float* __restrict__ w,
                                            const float* __restrict__ bias,
                                            float* __restrict__ out, int B) {
    __shared__ float s_w[10][1024];
    const int tid = threadIdx.x;
    float* sw = &s_w[0][0];
    for (int i = tid; i < 10 * 1024; i += 256) sw[i] = w[i];
    __syncthreads();

    const int warp = tid >> 5, lane = tid & 31;
    const int img = blockIdx.x * 8 + warp;
    if (img >= B) return;

    const float* xr = g_h3 + img * 1024;
    float acc[10];
#pragma unroll
    for (int o = 0; o < 10; ++o) acc[o] = 0.f;

    for (int j = 0; j < 32; ++j) {
        float xv = xr[j * 32 + lane];
#pragma unroll
        for (int o = 0; o < 10; ++o)
            acc[o] = fmaf(xv, s_w[o][j * 32 + lane], acc[o]);
    }
#pragma unroll
    for (int o = 0; o < 10; ++o) {
#pragma unroll
        for (int off = 16; off; off >>= 1)
            acc[o] += __shfl_down_sync(0xffffffffu, acc[o], off);
    }
    if (lane == 0) {
#pragma unroll
        for (int o = 0; o < 10; ++o) out[img * 10 + o] = acc[o] + bias[o];
    }
}

// ---------------------------------------------------------------------------
extern "C" void kernel_launch(void* const* d_in, const int* in_sizes, int n_in,
                              void* d_out, int out_size) {
    const float* x  = (const float*)d_in[0];
    const float* w1 = (const float*)d_in[1];
    const float* b1 = (const float*)d_in[2];
    const float* w2 = (const float*)d_in[3];
    const float* b2 = (const float*)d_in[4];
    const float* w3 = (const float*)d_in[5];
    const float* b3 = (const float*)d_in[6];
    const float* fw = (const float*)d_in[7];
    const float* fb = (const float*)d_in[8];
    float* out = (float*)d_out;

    const int B = in_sizes[0] / (3 * 32 * 32);

    cudaFuncSetAttribute(conv2_mma, cudaFuncAttributeMaxDynamicSharedMemorySize, C2_SMEM);
    cudaFuncSetAttribute(conv3_mma, cudaFuncAttributeMaxDynamicSharedMemorySize, C3_SMEM);
    cudaFuncSetAttribute(conv2_mma, cudaFuncAttributePreferredSharedMemoryCarveout, 100);
    cudaFuncSetAttribute(conv3_mma, cudaFuncAttributePreferredSharedMemoryCarveout, 100);

    w2prep_k<<<9, 256>>>(w2);
    w3prep_k<<<36, 256>>>(w3);
    conv1_k<<<B, 256>>>(x, w1, b1);
    conv2_mma<<<B, 256, C2_SMEM>>>(b2);
    conv3_mma<<<B, 256, C3_SMEM>>>(b3);
    fc_k<<<(B + 7) / 8, 256>>>(fw, fb, out, B);
}

// round 8
// speedup vs baseline: 2.1705x; 1.4417x over previous
#include <cuda_runtime.h>
#include <cuda_fp16.h>
#include <cstdint>

// ---------------------------------------------------------------------------
// ManualCNN round 7: persistent double-buffered mma convs (cp.async pipeline).
//   conv1: FFMA2 scalar, epilogue -> g_h1 fp16 hi/lo [324][8] half2 per image
//   conv2_p: persistent mma, cp.async A, -> g_h2 fp16 hi/lo [100][16] half2
//   conv3_p: persistent mma, cp.async A, -> g_h3 fp32 NCHW flatten
//   fc: warp-per-image
// 3-product fp16 split (Ahi*Bhi + Ahi*Blo + Alo*Bhi), fp32 accum.
// ---------------------------------------------------------------------------

#define B_MAX 4096

__device__ half2 g_h1hi[B_MAX * 2592];  // stage1 NHWC padded 18x18, 16ch (8 half2)
__device__ half2 g_h1lo[B_MAX * 2592];
__device__ half2 g_h2hi[B_MAX * 1600];  // stage2 NHWC padded 10x10, 32ch (16 half2)
__device__ half2 g_h2lo[B_MAX * 1600];
__device__ float g_h3[B_MAX * 1024];
__device__ uint4 g_w2pk[1152];          // [hi 576 | lo 576] fragment-packed w2
__device__ uint4 g_w3pk[4608];          // [hi 2304 | lo 2304] fragment-packed w3

typedef unsigned long long u64;

// ------------------------------ scalar helpers -----------------------------
__device__ __forceinline__ u64 pack2(float lo, float hi) {
    u64 r;
    asm("mov.b64 %0, {%1, %2};" : "=l"(r)
        : "r"(__float_as_uint(lo)), "r"(__float_as_uint(hi)));
    return r;
}
__device__ __forceinline__ u64 crossp(u64 a, u64 b) {
    u64 r;
    asm("mov.b64 %0, {%1, %2};" : "=l"(r)
        : "r"((unsigned)(a >> 32)), "r"((unsigned)b));
    return r;
}
__device__ __forceinline__ void fma2(u64& acc, u64 x, u64 w) {
    asm("fma.rn.f32x2 %0, %1, %2, %0;" : "+l"(acc) : "l"(x), "l"(w));
}
__device__ __forceinline__ float lo32(u64 a) { return __uint_as_float((unsigned)a); }
__device__ __forceinline__ float hi32(u64 a) { return __uint_as_float((unsigned)(a >> 32)); }

// ------------------------------- mma helpers -------------------------------
__device__ __forceinline__ void mma_f16(float d[4], const uint32_t a[4],
                                        uint32_t b0, uint32_t b1) {
    asm volatile(
        "mma.sync.aligned.m16n8k16.row.col.f32.f16.f16.f32 "
        "{%0,%1,%2,%3}, {%4,%5,%6,%7}, {%8,%9}, {%0,%1,%2,%3};"
        : "+f"(d[0]), "+f"(d[1]), "+f"(d[2]), "+f"(d[3])
        : "r"(a[0]), "r"(a[1]), "r"(a[2]), "r"(a[3]), "r"(b0), "r"(b1));
}
__device__ __forceinline__ void ldmx4(uint32_t r[4], uint32_t addr) {
    asm volatile("ldmatrix.sync.aligned.m8n8.x4.shared.b16 {%0,%1,%2,%3}, [%4];"
                 : "=r"(r[0]), "=r"(r[1]), "=r"(r[2]), "=r"(r[3]) : "r"(addr));
}
__device__ __forceinline__ uint32_t smem_u32(const void* p) {
    uint32_t a;
    asm("{ .reg .u64 t; cvta.to.shared.u64 t, %1; cvt.u32.u64 %0, t; }"
        : "=r"(a) : "l"(p));
    return a;
}
__device__ __forceinline__ void cp16(uint32_t dst, const void* src) {
    asm volatile("cp.async.cg.shared.global [%0], [%1], 16;"
                 :: "r"(dst), "l"(src) : "memory");
}
__device__ __forceinline__ void cp_commit() {
    asm volatile("cp.async.commit_group;" ::: "memory");
}
__device__ __forceinline__ void cp_wait1() {
    asm volatile("cp.async.wait_group 1;" ::: "memory");
}

// ---------------------------------------------------------------------------
// Stage 1: conv 3->16 on 32x32, pad1, relu, pool2 -> g_h1 hi/lo
// ---------------------------------------------------------------------------
__global__ __launch_bounds__(256) void conv1_k(const float* __restrict__ x,
                                               const float* __restrict__ w,
                                               const float* __restrict__ bias) {
    __shared__ __align__(16) float s_in[3][34][38];
    __shared__ float s_w[16 * 28];
    __shared__ float s_b[16];
    __shared__ __align__(16) float st[324 * 16];  // fp32 staging, NHWC 18x18

    const int b = blockIdx.x, tid = threadIdx.x;

    float* si = &s_in[0][0][0];
    for (int i = tid; i < 3 * 34 * 38; i += 256) si[i] = 0.f;
    for (int i = tid; i < 16 * 27; i += 256) s_w[(i / 27) * 28 + (i % 27)] = w[i];
    if (tid < 16) s_b[tid] = bias[tid];

    for (int i = tid; i < 1088; i += 256) {  // zero staging ring (68 px x 16)
        int hp = i >> 4, y, xx;
        if (hp < 18)      { y = 0;       xx = hp; }
        else if (hp < 36) { y = 17;      xx = hp - 18; }
        else if (hp < 52) { y = hp - 35; xx = 0; }
        else              { y = hp - 51; xx = 17; }
        st[(y * 18 + xx) * 16 + (i & 15)] = 0.f;
    }
    __syncthreads();

    const float* xb = x + b * 3 * 32 * 32;
    for (int i = tid; i < 3 * 32 * 32; i += 256) {
        int ic = i >> 10, r = (i >> 5) & 31, c = i & 31;
        s_in[ic][r + 1][c + 1] = xb[i];
    }
    __syncthreads();

    const int oc = tid & 15, py = tid >> 4;
    const float bb = s_b[oc];

#pragma unroll
    for (int h = 0; h < 2; ++h) {
        u64 P0[8], P1[8];
#pragma unroll
        for (int q = 0; q < 8; ++q) { P0[q] = 0ull; P1[q] = 0ull; }
#pragma unroll
        for (int ic = 0; ic < 3; ++ic) {
            u64 wp[9];
#pragma unroll
            for (int k = 0; k < 9; ++k) {
                float wv = s_w[oc * 28 + ic * 9 + k];
                wp[k] = pack2(wv, wv);
            }
#pragma unroll
            for (int r = 0; r < 4; ++r) {
                const float* row = &s_in[ic][2 * py + r][16 * h];
                u64 E[9], O[8];
#pragma unroll
                for (int j = 0; j < 9; ++j) E[j] = *(const u64*)(row + 2 * j);
#pragma unroll
                for (int j = 0; j < 8; ++j) O[j] = crossp(E[j], E[j + 1]);
                if (r < 3) {
#pragma unroll
                    for (int q = 0; q < 8; ++q) {
                        fma2(P0[q], E[q],     wp[r * 3 + 0]);
                        fma2(P0[q], O[q],     wp[r * 3 + 1]);
                        fma2(P0[q], E[q + 1], wp[r * 3 + 2]);
                    }
                }
                if (r > 0) {
#pragma unroll
                    for (int q = 0; q < 8; ++q) {
                        fma2(P1[q], E[q],     wp[(r - 1) * 3 + 0]);
                        fma2(P1[q], O[q],     wp[(r - 1) * 3 + 1]);
                        fma2(P1[q], E[q + 1], wp[(r - 1) * 3 + 2]);
                    }
                }
            }
        }
#pragma unroll
        for (int q = 0; q < 8; ++q) {
            float best = fmaxf(fmaxf(lo32(P0[q]), hi32(P0[q])),
                               fmaxf(lo32(P1[q]), hi32(P1[q])));
            st[((py + 1) * 18 + (8 * h + q + 1)) * 16 + oc] = fmaxf(best + bb, 0.f);
        }
    }
    __syncthreads();

    // convert staging -> g_h1 hi/lo half2 [324][8]
    for (int i = tid; i < 2592; i += 256) {
        int p = i >> 3, j = i & 7;
        float v0 = st[p * 16 + 2 * j], v1 = st[p * 16 + 2 * j + 1];
        half2 h = __floats2half2_rn(v0, v1);
        float2 hf = __half22float2(h);
        g_h1hi[b * 2592 + i] = h;
        g_h1lo[b * 2592 + i] = __floats2half2_rn(v0 - hf.x, v1 - hf.y);
    }
}

// ---------------------------------------------------------------------------
// Weight prep (unchanged layouts from R6)
// ---------------------------------------------------------------------------
__global__ __launch_bounds__(256) void w2prep_k(const float* __restrict__ w2) {
    int p = blockIdx.x * 256 + threadIdx.x;
    if (p >= 2304) return;
    int s = p >> 8, h = (p >> 7) & 1, l = (p >> 2) & 31, e = p & 3;
    int g = l >> 2, t = l & 3;
    int ky = s / 3, kx = s % 3;
    int oc = (h * 2 + (e >> 1)) * 8 + g;
    int k0 = 2 * t + 8 * (e & 1);
    float v0 = w2[((oc * 16 + k0)     * 3 + ky) * 3 + kx];
    float v1 = w2[((oc * 16 + k0 + 1) * 3 + ky) * 3 + kx];
    half2 hi = __floats2half2_rn(v0, v1);
    float2 hf = __half22float2(hi);
    ((half2*)g_w2pk)[p]        = hi;
    ((half2*)g_w2pk)[2304 + p] = __floats2half2_rn(v0 - hf.x, v1 - hf.y);
}
__global__ __launch_bounds__(256) void w3prep_k(const float* __restrict__ w3) {
    int p = blockIdx.x * 256 + threadIdx.x;
    if (p >= 9216) return;
    int sIdx = p >> 9, np = (p >> 7) & 3, l = (p >> 2) & 31, e = p & 3;
    int g = l >> 2, t = l & 3;
    int s = sIdx >> 1, kb = sIdx & 1;
    int ky = s / 3, kx = s % 3;
    int oc = np * 16 + (e >> 1) * 8 + g;
    int k0 = kb * 16 + 2 * t + 8 * (e & 1);
    float v0 = w3[((oc * 32 + k0)     * 3 + ky) * 3 + kx];
    float v1 = w3[((oc * 32 + k0 + 1) * 3 + ky) * 3 + kx];
    half2 hi = __floats2half2_rn(v0, v1);
    float2 hf = __half22float2(hi);
    ((half2*)g_w3pk)[p]        = hi;
    ((half2*)g_w3pk)[9216 + p] = __floats2half2_rn(v0 - hf.x, v1 - hf.y);
}

// ---------------------------------------------------------------------------
// Stage 2 persistent: conv 16->32, double-buffered cp.async pipeline.
// smem: [W 18432 | sb 128 | A[2]x(hi 15648 + lo 15648) | Sg 38016] = 119168 B
// ---------------------------------------------------------------------------
#define C2_SB_OFF 18432
#define C2_A_OFF  18560
#define C2_ALO    15648
#define C2_ABUF   31296
#define C2_SG_OFF 81152
#define C2_SMEM   119168

__global__ __launch_bounds__(256, 1) void conv2_p(const float* __restrict__ bias,
                                                  int B) {
    extern __shared__ __align__(16) char sm[];
    const uint4* W4 = (const uint4*)sm;
    float* sb = (float*)(sm + C2_SB_OFF);
    float* Sg = (float*)(sm + C2_SG_OFF);

    const int b0 = blockIdx.x, G = gridDim.x, tid = threadIdx.x;
    const int lane = tid & 31, wid = tid >> 5;
    const uint32_t smb = smem_u32(sm);

    {
        uint4* d = (uint4*)sm;
        for (int i = tid; i < 1152; i += 256) d[i] = g_w2pk[i];
    }
    if (tid < 32) sb[tid] = bias[tid];
    if (tid < 96) {  // zero A margins qp=0,325 (both buffers, hi+lo)
        int j = tid % 12, r = tid / 12;
        int qp = (r & 1) ? 325 : 0, kind = (r >> 1) & 1, buf = r >> 2;
        half2* p = (half2*)(sm + C2_A_OFF + buf * C2_ABUF + kind * C2_ALO);
        p[qp * 12 + j] = __floats2half2_rn(0.f, 0.f);
    }

    const int niter = (B - b0 + G - 1) / G;

    // prologue: prefetch image b0 into buffer 0
    {
        const uint4* shi = (const uint4*)(g_h1hi + b0 * 2592);
        const uint4* slo = (const uint4*)(g_h1lo + b0 * 2592);
        uint32_t dhi = smb + C2_A_OFF, dlo = dhi + C2_ALO;
        for (int i = tid; i < 648; i += 256) {
            uint32_t off = ((i >> 1) + 1) * 48 + (i & 1) * 16;
            cp16(dhi + off, shi + i);
            cp16(dlo + off, slo + i);
        }
    }
    cp_commit();

    for (int it = 0; it < niter; ++it) {
        const int img = b0 + it * G;
        const int nxt = img + G;
        if (nxt < B) {  // prefetch next image into the other buffer
            const uint4* shi = (const uint4*)(g_h1hi + nxt * 2592);
            const uint4* slo = (const uint4*)(g_h1lo + nxt * 2592);
            uint32_t dhi = smb + C2_A_OFF + ((it + 1) & 1) * C2_ABUF;
            uint32_t dlo = dhi + C2_ALO;
            for (int i = tid; i < 648; i += 256) {
                uint32_t off = ((i >> 1) + 1) * 48 + (i & 1) * 16;
                cp16(dhi + off, shi + i);
                cp16(dlo + off, slo + i);
            }
        }
        cp_commit();
        cp_wait1();
        __syncthreads();

        // ---- mainloop on buffer it&1
        const uint32_t aHiB = smb + C2_A_OFF + (it & 1) * C2_ABUF +
                              (lane & 15) * 48 + (lane >> 4) * 16;
        const uint32_t aLoB = aHiB + C2_ALO;

        float d[3][4][4];
#pragma unroll
        for (int i = 0; i < 3; ++i)
#pragma unroll
            for (int nt = 0; nt < 4; ++nt)
#pragma unroll
                for (int k = 0; k < 4; ++k) d[i][nt][k] = 0.f;

#pragma unroll
        for (int s = 0; s < 9; ++s) {
            const uint4 h0 = W4[(s * 2 + 0) * 32 + lane];
            const uint4 h1 = W4[(s * 2 + 1) * 32 + lane];
            const uint4 l0 = W4[576 + (s * 2 + 0) * 32 + lane];
            const uint4 l1 = W4[576 + (s * 2 + 1) * 32 + lane];
            const uint32_t bh[4][2] = {{h0.x, h0.y}, {h0.z, h0.w},
                                       {h1.x, h1.y}, {h1.z, h1.w}};
            const uint32_t bl[4][2] = {{l0.x, l0.y}, {l0.z, l0.w},
                                       {l1.x, l1.y}, {l1.z, l1.w}};
            const int rowc = (19 + (s / 3 - 1) * 18 + (s % 3 - 1)) * 48;
#pragma unroll
            for (int i = 0; i < 3; ++i) {
                const int mt = wid + 8 * i;
                if (mt < 18) {
                    uint32_t ah[4], al[4];
                    ldmx4(ah, aHiB + rowc + mt * 768);
                    ldmx4(al, aLoB + rowc + mt * 768);
#pragma unroll
                    for (int nt = 0; nt < 4; ++nt) {
                        mma_f16(d[i][nt], ah, bh[nt][0], bh[nt][1]);
                        mma_f16(d[i][nt], ah, bl[nt][0], bl[nt][1]);
                        mma_f16(d[i][nt], al, bh[nt][0], bh[nt][1]);
                    }
                }
            }
        }
        __syncthreads();

        // ---- epilogue: bias+relu -> Sg
        const int g = lane >> 2, t = lane & 3;
#pragma unroll
        for (int i = 0; i < 3; ++i) {
            const int mt = wid + 8 * i;
            if (mt < 18) {
                const int row = 16 * mt + g;
#pragma unroll
                for (int nt = 0; nt < 4; ++nt) {
                    const int col = nt * 8 + 2 * t;
                    Sg[row * 33 + col]           = fmaxf(d[i][nt][0] + sb[col], 0.f);
                    Sg[row * 33 + col + 1]       = fmaxf(d[i][nt][1] + sb[col + 1], 0.f);
                    Sg[(row + 8) * 33 + col]     = fmaxf(d[i][nt][2] + sb[col], 0.f);
                    Sg[(row + 8) * 33 + col + 1] = fmaxf(d[i][nt][3] + sb[col + 1], 0.f);
                }
            }
        }
        __syncthreads();

        // ---- pool -> g_h2 hi/lo (+ ring zeros)
        for (int e = tid; e < 1024; e += 256) {
            int oc2 = e & 15, pp = e >> 4;
            int py = pp >> 3, px = pp & 7;
            int r0 = 18 * (2 * py + 1) + (2 * px + 1) - 18;
            int c0 = 2 * oc2;
            float v0 = fmaxf(fmaxf(Sg[r0 * 33 + c0], Sg[(r0 + 1) * 33 + c0]),
                             fmaxf(Sg[(r0 + 18) * 33 + c0], Sg[(r0 + 19) * 33 + c0]));
            float v1 = fmaxf(fmaxf(Sg[r0 * 33 + c0 + 1], Sg[(r0 + 1) * 33 + c0 + 1]),
                             fmaxf(Sg[(r0 + 18) * 33 + c0 + 1], Sg[(r0 + 19) * 33 + c0 + 1]));
            half2 h = __floats2half2_rn(v0, v1);
            float2 hf = __half22float2(h);
            int gi = img * 1600 + ((py + 1) * 10 + (px + 1)) * 16 + oc2;
            g_h2hi[gi] = h;
            g_h2lo[gi] = __floats2half2_rn(v0 - hf.x, v1 - hf.y);
        }
        for (int i = tid; i < 576; i += 256) {  // ring (36 px x 16 half2)
            int hp = i >> 4, c = i & 15, y, xx;
            if (hp < 10)      { y = 0;       xx = hp; }
            else if (hp < 20) { y = 9;       xx = hp - 10; }
            else if (hp < 28) { y = hp - 19; xx = 0; }
            else              { y = hp - 27; xx = 9; }
            int gi = img * 1600 + (y * 10 + xx) * 16 + c;
            g_h2hi[gi] = __floats2half2_rn(0.f, 0.f);
            g_h2lo[gi] = __floats2half2_rn(0.f, 0.f);
        }
    }
}

// ---------------------------------------------------------------------------
// Stage 3 persistent: conv 32->64, double-buffered cp.async pipeline.
// smem: [W 73728 | sb 256 | A[2]x(hi 9440 + lo 9440) | Sg 24960] = 136704 B
// ---------------------------------------------------------------------------
#define C3_SB_OFF 73728
#define C3_A_OFF  73984
#define C3_ALO    9440
#define C3_ABUF   18880
#define C3_SG_OFF 111744
#define C3_SMEM   136704

__global__ __launch_bounds__(256, 1) void conv3_p(const float* __restrict__ bias,
                                                  int B) {
    extern __shared__ __align__(16) char sm[];
    const uint4* W4 = (const uint4*)sm;
    float* sb = (float*)(sm + C3_SB_OFF);
    float* Sg = (float*)(sm + C3_SG_OFF);

    const int b0 = blockIdx.x, G = gridDim.x, tid = threadIdx.x;
    const int lane = tid & 31, wid = tid >> 5;
    const uint32_t smb = smem_u32(sm);

    {
        uint4* d = (uint4*)sm;
        for (int i = tid; i < 4608; i += 256) d[i] = g_w3pk[i];
    }
    if (tid < 64) sb[tid] = bias[tid];
    for (int i = tid; i < 1440; i += 256) {  // zero A margins qp 0..2, 103..117
        int j = i % 20, r = i / 20;          // r 0..71
        int pxi = r % 18, kb = r / 18;       // kb 0..3
        int qp = (pxi < 3) ? pxi : (100 + pxi);
        half2* p = (half2*)(sm + C3_A_OFF + (kb >> 1) * C3_ABUF + (kb & 1) * C3_ALO);
        p[qp * 20 + j] = __floats2half2_rn(0.f, 0.f);
    }

    const int niter = (B - b0 + G - 1) / G;

    {
        const uint4* shi = (const uint4*)(g_h2hi + b0 * 1600);
        const uint4* slo = (const uint4*)(g_h2lo + b0 * 1600);
        uint32_t dhi = smb + C3_A_OFF, dlo = dhi + C3_ALO;
        for (int i = tid; i < 400; i += 256) {
            uint32_t off = ((i >> 2) + 3) * 80 + (i & 3) * 16;
            cp16(dhi + off, shi + i);
            cp16(dlo + off, slo + i);
        }
    }
    cp_commit();

    for (int it = 0; it < niter; ++it) {
        const int img = b0 + it * G;
        const int nxt = img + G;
        if (nxt < B) {
            const uint4* shi = (const uint4*)(g_h2hi + nxt * 1600);
            const uint4* slo = (const uint4*)(g_h2lo + nxt * 1600);
            uint32_t dhi = smb + C3_A_OFF + ((it + 1) & 1) * C3_ABUF;
            uint32_t dlo = dhi + C3_ALO;
            for (int i = tid; i < 400; i += 256) {
                uint32_t off = ((i >> 2) + 3) * 80 + (i & 3) * 16;
                cp16(dhi + off, shi + i);
                cp16(dlo + off, slo + i);
            }
        }
        cp_commit();
        cp_wait1();
        __syncthreads();

        const uint32_t aHiB = smb + C3_A_OFF + (it & 1) * C3_ABUF +
                              (lane & 15) * 80 + (lane >> 4) * 16;
        const uint32_t aLoB = aHiB + C3_ALO;
        const int np = wid & 3, mh = wid >> 2;

        float d[3][2][4];
#pragma unroll
        for (int i = 0; i < 3; ++i)
#pragma unroll
            for (int nt = 0; nt < 2; ++nt)
#pragma unroll
                for (int k = 0; k < 4; ++k) d[i][nt][k] = 0.f;

#pragma unroll
        for (int sIdx = 0; sIdx < 18; ++sIdx) {
            const int s = sIdx >> 1, kb = sIdx & 1;
            const uint4 h4 = W4[(sIdx * 4 + np) * 32 + lane];
            const uint4 l4 = W4[2304 + (sIdx * 4 + np) * 32 + lane];
            const uint32_t bh[2][2] = {{h4.x, h4.y}, {h4.z, h4.w}};
            const uint32_t bl[2][2] = {{l4.x, l4.y}, {l4.z, l4.w}};
            const int rowc = (11 + (s / 3 - 1) * 10 + (s % 3 - 1)) * 80 + kb * 32;
#pragma unroll
            for (int i = 0; i < 3; ++i) {
                const int mt = mh + 2 * i;
                uint32_t ah[4], al[4];
                ldmx4(ah, aHiB + rowc + mt * 1280);
                ldmx4(al, aLoB + rowc + mt * 1280);
#pragma unroll
                for (int nt = 0; nt < 2; ++nt) {
                    mma_f16(d[i][nt], ah, bh[nt][0], bh[nt][1]);
                    mma_f16(d[i][nt], ah, bl[nt][0], bl[nt][1]);
                    mma_f16(d[i][nt], al, bh[nt][0], bh[nt][1]);
                }
            }
        }
        __syncthreads();

        const int g = lane >> 2, t = lane & 3;
#pragma unroll
        for (int i = 0; i < 3; ++i) {
            const int row = 16 * (mh + 2 * i) + g;
#pragma unroll
            for (int nt = 0; nt < 2; ++nt) {
                const int col = np * 16 + nt * 8 + 2 * t;
                Sg[row * 65 + col]           = fmaxf(d[i][nt][0] + sb[col], 0.f);
                Sg[row * 65 + col + 1]       = fmaxf(d[i][nt][1] + sb[col + 1], 0.f);
                Sg[(row + 8) * 65 + col]     = fmaxf(d[i][nt][2] + sb[col], 0.f);
                Sg[(row + 8) * 65 + col + 1] = fmaxf(d[i][nt][3] + sb[col + 1], 0.f);
            }
        }
        __syncthreads();

        for (int e = tid; e < 1024; e += 256) {  // pool -> g_h3 NCHW flatten
            int oc = e >> 4, pp = e & 15, py = pp >> 2, px = pp & 3;
            int r0 = 10 * (2 * py + 1) + (2 * px + 1) - 8;
            float v = fmaxf(fmaxf(Sg[r0 * 65 + oc], Sg[(r0 + 1) * 65 + oc]),
                            fmaxf(Sg[(r0 + 10) * 65 + oc], Sg[(r0 + 11) * 65 + oc]));
            g_h3[img * 1024 + oc * 16 + pp] = v;
        }
    }
}

// ---------------------------------------------------------------------------
// FC: [B,1024] @ fc_w^T + fc_b. One warp per image, 8 images/block.
// ---------------------------------------------------------------------------
__global__ __launch_bounds__(256) void fc_k(const float* __restrict__ w,
                                            const float* __restrict__ bias,
                                            float* __restrict__ out, int B) {
    __shared__ float s_w[10][1024];
    const int tid = threadIdx.x;
    float* sw = &s_w[0][0];
    for (int i = tid; i < 10 * 1024; i += 256) sw[i] = w[i];
    __syncthreads();

    const int warp = tid >> 5, lane = tid & 31;
    const int img = blockIdx.x * 8 + warp;
    if (img >= B) return;

    const float* xr = g_h3 + img * 1024;
    float acc[10];
#pragma unroll
    for (int o = 0; o < 10; ++o) acc[o] = 0.f;

    for (int j = 0; j < 32; ++j) {
        float xv = xr[j * 32 + lane];
#pragma unroll
        for (int o = 0; o < 10; ++o)
            acc[o] = fmaf(xv, s_w[o][j * 32 + lane], acc[o]);
    }
#pragma unroll
    for (int o = 0; o < 10; ++o) {
#pragma unroll
        for (int off = 16; off; off >>= 1)
            acc[o] += __shfl_down_sync(0xffffffffu, acc[o], off);
    }
    if (lane == 0) {
#pragma unroll
        for (int o = 0; o < 10; ++o) out[img * 10 + o] = acc[o] + bias[o];
    }
}

// ---------------------------------------------------------------------------
extern "C" void kernel_launch(void* const* d_in, const int* in_sizes, int n_in,
                              void* d_out, int out_size) {
    const float* x  = (const float*)d_in[0];
    const float* w1 = (const float*)d_in[1];
    const float* b1 = (const float*)d_in[2];
    const float* w2 = (const float*)d_in[3];
    const float* b2 = (const float*)d_in[4];
    const float* w3 = (const float*)d_in[5];
    const float* b3 = (const float*)d_in[6];
    const float* fw = (const float*)d_in[7];
    const float* fb = (const float*)d_in[8];
    float* out = (float*)d_out;

    const int B = in_sizes[0] / (3 * 32 * 32);
    const int G = 148;

    cudaFuncSetAttribute(conv2_p, cudaFuncAttributeMaxDynamicSharedMemorySize, C2_SMEM);
    cudaFuncSetAttribute(conv3_p, cudaFuncAttributeMaxDynamicSharedMemorySize, C3_SMEM);

    w2prep_k<<<9, 256>>>(w2);
    w3prep_k<<<36, 256>>>(w3);
    conv1_k<<<B, 256>>>(x, w1, b1);
    conv2_p<<<G, 256, C2_SMEM>>>(b2, B);
    conv3_p<<<G, 256, C3_SMEM>>>(b3, B);
    fc_k<<<(B + 7) / 8, 256>>>(fw, fb, out, B);
}

// round 13
// speedup vs baseline: 2.3965x; 1.1041x over previous
#include <cuda_runtime.h>
#include <cuda_fp16.h>
#include <cstdint>

// ---------------------------------------------------------------------------
// ManualCNN round 8: software-pipelined mma mainloops, FC fused into conv3,
// conv1 at 512 threads.
//   conv1: FFMA2 scalar (512 thr) -> g_h1 fp16 hi/lo
//   conv2_p: persistent mma (288 thr, pipelined) -> g_h2 fp16 hi/lo
//   conv3_p: persistent mma (256 thr, pipelined) + fused FC -> out
// 3-product fp16 split (Ahi*Bhi + Ahi*Blo + Alo*Bhi), fp32 accum.
// ---------------------------------------------------------------------------

#define B_MAX 4096

__device__ half2 g_h1hi[B_MAX * 2592];  // stage1 NHWC padded 18x18, 16ch
__device__ half2 g_h1lo[B_MAX * 2592];
__device__ half2 g_h2hi[B_MAX * 1600];  // stage2 NHWC padded 10x10, 32ch
__device__ half2 g_h2lo[B_MAX * 1600];
__device__ uint4 g_w2pk[1152];          // [hi 576 | lo 576] fragment-packed w2
__device__ uint4 g_w3pk[4608];          // [hi 2304 | lo 2304] fragment-packed w3

typedef unsigned long long u64;

// ------------------------------ scalar helpers -----------------------------
__device__ __forceinline__ u64 pack2(float lo, float hi) {
    u64 r;
    asm("mov.b64 %0, {%1, %2};" : "=l"(r)
        : "r"(__float_as_uint(lo)), "r"(__float_as_uint(hi)));
    return r;
}
__device__ __forceinline__ u64 crossp(u64 a, u64 b) {
    u64 r;
    asm("mov.b64 %0, {%1, %2};" : "=l"(r)
        : "r"((unsigned)(a >> 32)), "r"((unsigned)b));
    return r;
}
__device__ __forceinline__ void fma2(u64& acc, u64 x, u64 w) {
    asm("fma.rn.f32x2 %0, %1, %2, %0;" : "+l"(acc) : "l"(x), "l"(w));
}
__device__ __forceinline__ float lo32(u64 a) { return __uint_as_float((unsigned)a); }
__device__ __forceinline__ float hi32(u64 a) { return __uint_as_float((unsigned)(a >> 32)); }

// ------------------------------- mma helpers -------------------------------
__device__ __forceinline__ void mma_f16(float d[4], const uint32_t a[4],
                                        uint32_t b0, uint32_t b1) {
    asm volatile(
        "mma.sync.aligned.m16n8k16.row.col.f32.f16.f16.f32 "
        "{%0,%1,%2,%3}, {%4,%5,%6,%7}, {%8,%9}, {%0,%1,%2,%3};"
        : "+f"(d[0]), "+f"(d[1]), "+f"(d[2]), "+f"(d[3])
        : "r"(a[0]), "r"(a[1]), "r"(a[2]), "r"(a[3]), "r"(b0), "r"(b1));
}
__device__ __forceinline__ void ldmx4(uint32_t r[4], uint32_t addr) {
    asm volatile("ldmatrix.sync.aligned.m8n8.x4.shared.b16 {%0,%1,%2,%3}, [%4];"
                 : "=r"(r[0]), "=r"(r[1]), "=r"(r[2]), "=r"(r[3]) : "r"(addr));
}
__device__ __forceinline__ uint32_t smem_u32(const void* p) {
    uint32_t a;
    asm("{ .reg .u64 t; cvta.to.shared.u64 t, %1; cvt.u32.u64 %0, t; }"
        : "=r"(a) : "l"(p));
    return a;
}
__device__ __forceinline__ void cp16(uint32_t dst, const void* src) {
    asm volatile("cp.async.cg.shared.global [%0], [%1], 16;"
                 :: "r"(dst), "l"(src) : "memory");
}
__device__ __forceinline__ void cp_commit() {
    asm volatile("cp.async.commit_group;" ::: "memory");
}
__device__ __forceinline__ void cp_wait1() {
    asm volatile("cp.async.wait_group 1;" ::: "memory");
}

// ---------------------------------------------------------------------------
// Stage 1: conv 3->16 on 32x32, pad1, relu, pool2 -> g_h1 hi/lo. 512 threads:
// (oc = tid&15, py = (tid>>4)&15, h = tid>>8), each thread one 8-px half.
// ---------------------------------------------------------------------------
__global__ __launch_bounds__(512) void conv1_k(const float* __restrict__ x,
                                               const float* __restrict__ w,
                                               const float* __restrict__ bias) {
    __shared__ __align__(16) float s_in[3][34][38];
    __shared__ float s_w[16 * 28];
    __shared__ float s_b[16];
    __shared__ __align__(16) float st[324 * 16];

    const int b = blockIdx.x, tid = threadIdx.x;

    float* si = &s_in[0][0][0];
    for (int i = tid; i < 3 * 34 * 38; i += 512) si[i] = 0.f;
    if (tid < 432) s_w[(tid / 27) * 28 + (tid % 27)] = w[tid];
    if (tid < 16) s_b[tid] = bias[tid];

    for (int i = tid; i < 1088; i += 512) {  // zero staging ring
        int hp = i >> 4, y, xx;
        if (hp < 18)      { y = 0;       xx = hp; }
        else if (hp < 36) { y = 17;      xx = hp - 18; }
        else if (hp < 52) { y = hp - 35; xx = 0; }
        else              { y = hp - 51; xx = 17; }
        st[(y * 18 + xx) * 16 + (i & 15)] = 0.f;
    }
    __syncthreads();

    const float* xb = x + b * 3 * 32 * 32;
    for (int i = tid; i < 3 * 32 * 32; i += 512) {
        int ic = i >> 10, r = (i >> 5) & 31, c = i & 31;
        s_in[ic][r + 1][c + 1] = xb[i];
    }
    __syncthreads();

    const int oc = tid & 15, py = (tid >> 4) & 15, h = tid >> 8;
    const float bb = s_b[oc];

    u64 P0[8], P1[8];
#pragma unroll
    for (int q = 0; q < 8; ++q) { P0[q] = 0ull; P1[q] = 0ull; }
#pragma unroll
    for (int ic = 0; ic < 3; ++ic) {
        u64 wp[9];
#pragma unroll
        for (int k = 0; k < 9; ++k) {
            float wv = s_w[oc * 28 + ic * 9 + k];
            wp[k] = pack2(wv, wv);
        }
#pragma unroll
        for (int r = 0; r < 4; ++r) {
            const float* row = &s_in[ic][2 * py + r][16 * h];
            u64 E[9], O[8];
#pragma unroll
            for (int j = 0; j < 9; ++j) E[j] = *(const u64*)(row + 2 * j);
#pragma unroll
            for (int j = 0; j < 8; ++j) O[j] = crossp(E[j], E[j + 1]);
            if (r < 3) {
#pragma unroll
                for (int q = 0; q < 8; ++q) {
                    fma2(P0[q], E[q],     wp[r * 3 + 0]);
                    fma2(P0[q], O[q],     wp[r * 3 + 1]);
                    fma2(P0[q], E[q + 1], wp[r * 3 + 2]);
                }
            }
            if (r > 0) {
#pragma unroll
                for (int q = 0; q < 8; ++q) {
                    fma2(P1[q], E[q],     wp[(r - 1) * 3 + 0]);
                    fma2(P1[q], O[q],     wp[(r - 1) * 3 + 1]);
                    fma2(P1[q], E[q + 1], wp[(r - 1) * 3 + 2]);
                }
            }
        }
    }
#pragma unroll
    for (int q = 0; q < 8; ++q) {
        float best = fmaxf(fmaxf(lo32(P0[q]), hi32(P0[q])),
                           fmaxf(lo32(P1[q]), hi32(P1[q])));
        st[((py + 1) * 18 + (8 * h + q + 1)) * 16 + oc] = fmaxf(best + bb, 0.f);
    }
    __syncthreads();

    for (int i = tid; i < 2592; i += 512) {
        int p = i >> 3, j = i & 7;
        float v0 = st[p * 16 + 2 * j], v1 = st[p * 16 + 2 * j + 1];
        half2 hh = __floats2half2_rn(v0, v1);
        float2 hf = __half22float2(hh);
        g_h1hi[b * 2592 + i] = hh;
        g_h1lo[b * 2592 + i] = __floats2half2_rn(v0 - hf.x, v1 - hf.y);
    }
}

// ---------------------------------------------------------------------------
// Weight prep (layouts unchanged from R6/R7)
// ---------------------------------------------------------------------------
__global__ __launch_bounds__(256) void w2prep_k(const float* __restrict__ w2) {
    int p = blockIdx.x * 256 + threadIdx.x;
    if (p >= 2304) return;
    int s = p >> 8, h = (p >> 7) & 1, l = (p >> 2) & 31, e = p & 3;
    int g = l >> 2, t = l & 3;
    int ky = s / 3, kx = s % 3;
    int oc = (h * 2 + (e >> 1)) * 8 + g;
    int k0 = 2 * t + 8 * (e & 1);
    float v0 = w2[((oc * 16 + k0)     * 3 + ky) * 3 + kx];
    float v1 = w2[((oc * 16 + k0 + 1) * 3 + ky) * 3 + kx];
    half2 hi = __floats2half2_rn(v0, v1);
    float2 hf = __half22float2(hi);
    ((half2*)g_w2pk)[p]        = hi;
    ((half2*)g_w2pk)[2304 + p] = __floats2half2_rn(v0 - hf.x, v1 - hf.y);
}
__global__ __launch_bounds__(256) void w3prep_k(const float* __restrict__ w3) {
    int p = blockIdx.x * 256 + threadIdx.x;
    if (p >= 9216) return;
    int sIdx = p >> 9, np = (p >> 7) & 3, l = (p >> 2) & 31, e = p & 3;
    int g = l >> 2, t = l & 3;
    int s = sIdx >> 1, kb = sIdx & 1;
    int ky = s / 3, kx = s % 3;
    int oc = np * 16 + (e >> 1) * 8 + g;
    int k0 = kb * 16 + 2 * t + 8 * (e & 1);
    float v0 = w3[((oc * 32 + k0)     * 3 + ky) * 3 + kx];
    float v1 = w3[((oc * 32 + k0 + 1) * 3 + ky) * 3 + kx];
    half2 hi = __floats2half2_rn(v0, v1);
    float2 hf = __half22float2(hi);
    ((half2*)g_w3pk)[p]        = hi;
    ((half2*)g_w3pk)[9216 + p] = __floats2half2_rn(v0 - hf.x, v1 - hf.y);
}

// ---------------------------------------------------------------------------
// Stage 2 persistent: conv 16->32, 288 thr / 9 warps, pipelined mainloop.
// Warp w: all 32 oc, m-tiles {2w, 2w+1}. A pixel stride 48B.
// ---------------------------------------------------------------------------
#define C2_SB_OFF 18432
#define C2_A_OFF  18560
#define C2_ALO    15648
#define C2_ABUF   31296
#define C2_SG_OFF 81152
#define C2_SMEM   119168
#define RC2(s) ((19 + ((s) / 3 - 1) * 18 + ((s) % 3 - 1)) * 48)

__global__ __launch_bounds__(288, 1) void conv2_p(const float* __restrict__ bias,
                                                  int B) {
    extern __shared__ __align__(16) char sm[];
    const uint4* W4 = (const uint4*)sm;
    float* sb = (float*)(sm + C2_SB_OFF);
    float* Sg = (float*)(sm + C2_SG_OFF);

    const int b0 = blockIdx.x, G = gridDim.x, tid = threadIdx.x;
    const int lane = tid & 31, wid = tid >> 5;
    const uint32_t smb = smem_u32(sm);

    {
        uint4* d = (uint4*)sm;
        for (int i = tid; i < 1152; i += 288) d[i] = g_w2pk[i];
    }
    if (tid < 32) sb[tid] = bias[tid];
    if (tid < 96) {  // zero A margins qp=0,325 (both buffers, hi+lo)
        int j = tid % 12, r = tid / 12;
        int qp = (r & 1) ? 325 : 0, kind = (r >> 1) & 1, buf = r >> 2;
        half2* p = (half2*)(sm + C2_A_OFF + buf * C2_ABUF + kind * C2_ALO);
        p[qp * 12 + j] = __floats2half2_rn(0.f, 0.f);
    }

    const int niter = (B - b0 + G - 1) / G;

    {
        const uint4* shi = (const uint4*)(g_h1hi + b0 * 2592);
        const uint4* slo = (const uint4*)(g_h1lo + b0 * 2592);
        uint32_t dhi = smb + C2_A_OFF, dlo = dhi + C2_ALO;
        for (int i = tid; i < 648; i += 288) {
            uint32_t off = ((i >> 1) + 1) * 48 + (i & 1) * 16;
            cp16(dhi + off, shi + i);
            cp16(dlo + off, slo + i);
        }
    }
    cp_commit();

    for (int it = 0; it < niter; ++it) {
        const int img = b0 + it * G;
        const int nxt = img + G;
        if (nxt < B) {
            const uint4* shi = (const uint4*)(g_h1hi + nxt * 2592);
            const uint4* slo = (const uint4*)(g_h1lo + nxt * 2592);
            uint32_t dhi = smb + C2_A_OFF + ((it + 1) & 1) * C2_ABUF;
            uint32_t dlo = dhi + C2_ALO;
            for (int i = tid; i < 648; i += 288) {
                uint32_t off = ((i >> 1) + 1) * 48 + (i & 1) * 16;
                cp16(dhi + off, shi + i);
                cp16(dlo + off, slo + i);
            }
        }
        cp_commit();
        cp_wait1();
        __syncthreads();

        const uint32_t aHiB = smb + C2_A_OFF + (it & 1) * C2_ABUF +
                              (lane & 15) * 48 + (lane >> 4) * 16;
        const uint32_t aLoB = aHiB + C2_ALO;
        const int mt0 = 2 * wid;

        float d[2][4][4];
#pragma unroll
        for (int i = 0; i < 2; ++i)
#pragma unroll
            for (int nt = 0; nt < 4; ++nt)
#pragma unroll
                for (int k = 0; k < 4; ++k) d[i][nt][k] = 0.f;

        uint32_t ah[2][4], al[2][4];
        uint4 Wb[2][4];
        ldmx4(ah[0], aHiB + RC2(0) + mt0 * 768);
        ldmx4(al[0], aLoB + RC2(0) + mt0 * 768);
        Wb[0][0] = W4[0 * 32 + lane];
        Wb[0][1] = W4[1 * 32 + lane];
        Wb[0][2] = W4[576 + 0 * 32 + lane];
        Wb[0][3] = W4[576 + 1 * 32 + lane];

#pragma unroll
        for (int s = 0; s < 9; ++s) {
            const int cw = s & 1, nw = cw ^ 1;
            if (s < 8) {
                Wb[nw][0] = W4[((s + 1) * 2 + 0) * 32 + lane];
                Wb[nw][1] = W4[((s + 1) * 2 + 1) * 32 + lane];
                Wb[nw][2] = W4[576 + ((s + 1) * 2 + 0) * 32 + lane];
                Wb[nw][3] = W4[576 + ((s + 1) * 2 + 1) * 32 + lane];
            }
#pragma unroll
            for (int i = 0; i < 2; ++i) {
                const int stp = 2 * s + i, p = stp & 1, pn = p ^ 1;
                if (stp + 1 < 18) {
                    const int ns = (i == 0) ? s : s + 1;
                    const int nmt = (i == 0) ? mt0 + 1 : mt0;
                    ldmx4(ah[pn], aHiB + RC2(ns) + nmt * 768);
                    ldmx4(al[pn], aLoB + RC2(ns) + nmt * 768);
                }
                mma_f16(d[i][0], ah[p], Wb[cw][0].x, Wb[cw][0].y);
                mma_f16(d[i][0], ah[p], Wb[cw][2].x, Wb[cw][2].y);
                mma_f16(d[i][0], al[p], Wb[cw][0].x, Wb[cw][0].y);
                mma_f16(d[i][1], ah[p], Wb[cw][0].z, Wb[cw][0].w);
                mma_f16(d[i][1], ah[p], Wb[cw][2].z, Wb[cw][2].w);
                mma_f16(d[i][1], al[p], Wb[cw][0].z, Wb[cw][0].w);
                mma_f16(d[i][2], ah[p], Wb[cw][1].x, Wb[cw][1].y);
                mma_f16(d[i][2], ah[p], Wb[cw][3].x, Wb[cw][3].y);
                mma_f16(d[i][2], al[p], Wb[cw][1].x, Wb[cw][1].y);
                mma_f16(d[i][3], ah[p], Wb[cw][1].z, Wb[cw][1].w);
                mma_f16(d[i][3], ah[p], Wb[cw][3].z, Wb[cw][3].w);
                mma_f16(d[i][3], al[p], Wb[cw][1].z, Wb[cw][1].w);
            }
        }
        __syncthreads();

        const int g = lane >> 2, t = lane & 3;
#pragma unroll
        for (int i = 0; i < 2; ++i) {
            const int row = 16 * (mt0 + i) + g;
#pragma unroll
            for (int nt = 0; nt < 4; ++nt) {
                const int col = nt * 8 + 2 * t;
                Sg[row * 33 + col]           = fmaxf(d[i][nt][0] + sb[col], 0.f);
                Sg[row * 33 + col + 1]       = fmaxf(d[i][nt][1] + sb[col + 1], 0.f);
                Sg[(row + 8) * 33 + col]     = fmaxf(d[i][nt][2] + sb[col], 0.f);
                Sg[(row + 8) * 33 + col + 1] = fmaxf(d[i][nt][3] + sb[col + 1], 0.f);
            }
        }
        __syncthreads();

        for (int e = tid; e < 1024; e += 288) {
            int oc2 = e & 15, pp = e >> 4;
            int py = pp >> 3, px = pp & 7;
            int r0 = 18 * (2 * py + 1) + (2 * px + 1) - 18;
            int c0 = 2 * oc2;
            float v0 = fmaxf(fmaxf(Sg[r0 * 33 + c0], Sg[(r0 + 1) * 33 + c0]),
                             fmaxf(Sg[(r0 + 18) * 33 + c0], Sg[(r0 + 19) * 33 + c0]));
            float v1 = fmaxf(fmaxf(Sg[r0 * 33 + c0 + 1], Sg[(r0 + 1) * 33 + c0 + 1]),
                             fmaxf(Sg[(r0 + 18) * 33 + c0 + 1], Sg[(r0 + 19) * 33 + c0 + 1]));
            half2 hh = __floats2half2_rn(v0, v1);
            float2 hf = __half22float2(hh);
            int gi = img * 1600 + ((py + 1) * 10 + (px + 1)) * 16 + oc2;
            g_h2hi[gi] = hh;
            g_h2lo[gi] = __floats2half2_rn(v0 - hf.x, v1 - hf.y);
        }
        for (int i = tid; i < 576; i += 288) {
            int hp = i >> 4, c = i & 15, y, xx;
            if (hp < 10)      { y = 0;       xx = hp; }
            else if (hp < 20) { y = 9;       xx = hp - 10; }
            else if (hp < 28) { y = hp - 19; xx = 0; }
            else              { y = hp - 27; xx = 9; }
            int gi = img * 1600 + (y * 10 + xx) * 16 + c;
            g_h2hi[gi] = __floats2half2_rn(0.f, 0.f);
            g_h2lo[gi] = __floats2half2_rn(0.f, 0.f);
        }
    }
}

// ---------------------------------------------------------------------------
// Stage 3 persistent + fused FC. 256 thr / 8 warps, pipelined mainloop.
// Warp w: np=w&3 (16 oc), mh=w>>2, m-tiles {mh, mh+2, mh+4}. A stride 80B.
// ---------------------------------------------------------------------------
#define C3_SB_OFF 73728
#define C3_FCB    73984
#define C3_RED    74048
#define C3_FCW    74368
#define C3_A_OFF  115328
#define C3_ALO    9440
#define C3_ABUF   18880
#define C3_SG_OFF 153088
#define C3_SMEM   178048
#define RC3(si) ((11 + (((si) >> 1) / 3 - 1) * 10 + (((si) >> 1) % 3 - 1)) * 80 + ((si) & 1) * 32)

__global__ __launch_bounds__(256, 1) void conv3_p(const float* __restrict__ bias,
                                                  const float* __restrict__ fw,
                                                  const float* __restrict__ fb,
                                                  float* __restrict__ out, int B) {
    extern __shared__ __align__(16) char sm[];
    const uint4* W4 = (const uint4*)sm;
    float* sb  = (float*)(sm + C3_SB_OFF);
    float* fcb = (float*)(sm + C3_FCB);
    float* red = (float*)(sm + C3_RED);
    float* fcw = (float*)(sm + C3_FCW);
    float* Sg  = (float*)(sm + C3_SG_OFF);

    const int b0 = blockIdx.x, G = gridDim.x, tid = threadIdx.x;
    const int lane = tid & 31, wid = tid >> 5;
    const uint32_t smb = smem_u32(sm);

    {
        uint4* d = (uint4*)sm;
        for (int i = tid; i < 4608; i += 256) d[i] = g_w3pk[i];
    }
    if (tid < 64) sb[tid] = bias[tid];
    if (tid < 10) fcb[tid] = fb[tid];
    for (int i = tid; i < 10240; i += 256) fcw[i] = fw[i];
    for (int i = tid; i < 1440; i += 256) {  // zero A margins qp 0..2, 103..117
        int j = i % 20, r = i / 20;
        int pxi = r % 18, kb = r / 18;
        int qp = (pxi < 3) ? pxi : (100 + pxi);
        half2* p = (half2*)(sm + C3_A_OFF + (kb >> 1) * C3_ABUF + (kb & 1) * C3_ALO);
        p[qp * 20 + j] = __floats2half2_rn(0.f, 0.f);
    }

    const int niter = (B - b0 + G - 1) / G;

    {
        const uint4* shi = (const uint4*)(g_h2hi + b0 * 1600);
        const uint4* slo = (const uint4*)(g_h2lo + b0 * 1600);
        uint32_t dhi = smb + C3_A_OFF, dlo = dhi + C3_ALO;
        for (int i = tid; i < 400; i += 256) {
            uint32_t off = ((i >> 2) + 3) * 80 + (i & 3) * 16;
            cp16(dhi + off, shi + i);
            cp16(dlo + off, slo + i);
        }
    }
    cp_commit();

    for (int it = 0; it < niter; ++it) {
        const int img = b0 + it * G;
        const int nxt = img + G;
        if (nxt < B) {
            const uint4* shi = (const uint4*)(g_h2hi + nxt * 1600);
            const uint4* slo = (const uint4*)(g_h2lo + nxt * 1600);
            uint32_t dhi = smb + C3_A_OFF + ((it + 1) & 1) * C3_ABUF;
            uint32_t dlo = dhi + C3_ALO;
            for (int i = tid; i < 400; i += 256) {
                uint32_t off = ((i >> 2) + 3) * 80 + (i & 3) * 16;
                cp16(dhi + off, shi + i);
                cp16(dlo + off, slo + i);
            }
        }
        cp_commit();
        cp_wait1();
        __syncthreads();

        const uint32_t aHiB = smb + C3_A_OFF + (it & 1) * C3_ABUF +
                              (lane & 15) * 80 + (lane >> 4) * 16;
        const uint32_t aLoB = aHiB + C3_ALO;
        const int np = wid & 3, mh = wid >> 2;

        float d[3][2][4];
#pragma unroll
        for (int i = 0; i < 3; ++i)
#pragma unroll
            for (int nt = 0; nt < 2; ++nt)
#pragma unroll
                for (int k = 0; k < 4; ++k) d[i][nt][k] = 0.f;

        uint32_t ah[2][4], al[2][4];
        uint4 Wb[2][2];
        ldmx4(ah[0], aHiB + RC3(0) + mh * 1280);
        ldmx4(al[0], aLoB + RC3(0) + mh * 1280);
        Wb[0][0] = W4[(0 * 4 + np) * 32 + lane];
        Wb[0][1] = W4[2304 + (0 * 4 + np) * 32 + lane];

#pragma unroll
        for (int sIdx = 0; sIdx < 18; ++sIdx) {
            const int cw = sIdx & 1, nw = cw ^ 1;
            if (sIdx < 17) {
                Wb[nw][0] = W4[((sIdx + 1) * 4 + np) * 32 + lane];
                Wb[nw][1] = W4[2304 + ((sIdx + 1) * 4 + np) * 32 + lane];
            }
#pragma unroll
            for (int i = 0; i < 3; ++i) {
                const int stp = 3 * sIdx + i, p = stp & 1, pn = p ^ 1;
                if (stp + 1 < 54) {
                    const int ns = (i == 2) ? sIdx + 1 : sIdx;
                    const int ni = (i == 2) ? 0 : i + 1;
                    ldmx4(ah[pn], aHiB + RC3(ns) + (mh + 2 * ni) * 1280);
                    ldmx4(al[pn], aLoB + RC3(ns) + (mh + 2 * ni) * 1280);
                }
                mma_f16(d[i][0], ah[p], Wb[cw][0].x, Wb[cw][0].y);
                mma_f16(d[i][0], ah[p], Wb[cw][1].x, Wb[cw][1].y);
                mma_f16(d[i][0], al[p], Wb[cw][0].x, Wb[cw][0].y);
                mma_f16(d[i][1], ah[p], Wb[cw][0].z, Wb[cw][0].w);
                mma_f16(d[i][1], ah[p], Wb[cw][1].z, Wb[cw][1].w);
                mma_f16(d[i][1], al[p], Wb[cw][0].z, Wb[cw][0].w);
            }
        }
        __syncthreads();

        const int g = lane >> 2, t = lane & 3;
#pragma unroll
        for (int i = 0; i < 3; ++i) {
            const int row = 16 * (mh + 2 * i) + g;
#pragma unroll
            for (int nt = 0; nt < 2; ++nt) {
                const int col = np * 16 + nt * 8 + 2 * t;
                Sg[row * 65 + col]           = fmaxf(d[i][nt][0] + sb[col], 0.f);
                Sg[row * 65 + col + 1]       = fmaxf(d[i][nt][1] + sb[col + 1], 0.f);
                Sg[(row + 8) * 65 + col]     = fmaxf(d[i][nt][2] + sb[col], 0.f);
                Sg[(row + 8) * 65 + col + 1] = fmaxf(d[i][nt][3] + sb[col + 1], 0.f);
            }
        }
        __syncthreads();

        // ---- pool + fused FC
        float acc[10];
#pragma unroll
        for (int o = 0; o < 10; ++o) acc[o] = 0.f;
        for (int e = tid; e < 1024; e += 256) {
            int oc = e >> 4, pp = e & 15, py = pp >> 2, px = pp & 3;
            int r0 = 10 * (2 * py + 1) + (2 * px + 1) - 8;
            float v = fmaxf(fmaxf(Sg[r0 * 65 + oc], Sg[(r0 + 1) * 65 + oc]),
                            fmaxf(Sg[(r0 + 10) * 65 + oc], Sg[(r0 + 11) * 65 + oc]));
#pragma unroll
            for (int o = 0; o < 10; ++o)
                acc[o] = fmaf(v, fcw[o * 1024 + e], acc[o]);
        }
#pragma unroll
        for (int o = 0; o < 10; ++o) {
#pragma unroll
            for (int off = 16; off; off >>= 1)
                acc[o] += __shfl_down_sync(0xffffffffu, acc[o], off);
        }
        if (lane == 0) {
#pragma unroll
            for (int o = 0; o < 10; ++o) red[wid * 10 + o] = acc[o];
        }
        __syncthreads();
        if (tid < 10) {
            float s2 = fcb[tid];
#pragma unroll
            for (int w8 = 0; w8 < 8; ++w8) s2 += red[w8 * 10 + tid];
            out[img * 10 + tid] = s2;
        }
    }
}

// ---------------------------------------------------------------------------
extern "C" void kernel_launch(void* const* d_in, const int* in_sizes, int n_in,
                              void* d_out, int out_size) {
    const float* x  = (const float*)d_in[0];
    const float* w1 = (const float*)d_in[1];
    const float* b1 = (const float*)d_in[2];
    const float* w2 = (const float*)d_in[3];
    const float* b2 = (const float*)d_in[4];
    const float* w3 = (const float*)d_in[5];
    const float* b3 = (const float*)d_in[6];
    const float* fw = (const float*)d_in[7];
    const float* fb = (const float*)d_in[8];
    float* out = (float*)d_out;

    const int B = in_sizes[0] / (3 * 32 * 32);
    const int G = 148;

    cudaFuncSetAttribute(conv2_p, cudaFuncAttributeMaxDynamicSharedMemorySize, C2_SMEM);
    cudaFuncSetAttribute(conv3_p, cudaFuncAttributeMaxDynamicSharedMemorySize, C3_SMEM);

    w2prep_k<<<9, 256>>>(w2);
    w3prep_k<<<36, 256>>>(w3);
    conv1_k<<<B, 512>>>(x, w1, b1);
    conv2_p<<<G, 288, C2_SMEM>>>(b2, B);
    conv3_p<<<G, 256, C3_SMEM>>>(b3, fw, fb, out, B);
}